// round 6
// baseline (speedup 1.0000x reference)
#include <cuda_runtime.h>
#include <math.h>

#define TWO_PI_F 6.2831853071795864769f

// ---------------- device scratch ----------------
__device__ float d_h0[64*64*64*64];      // [64,64,64,64]
__device__ float d_h1[64*128*32*32];     // [64,128,32,32]
__device__ float d_Zbuf[64*168*16*16];   // [64,168,16,16]
__device__ float d_g0[64*256*32*32];     // [64,256,32,32]
__device__ float d_g1[64*128*64*64];     // [64,128,64,64]
__device__ float d_stat0[128];
__device__ float d_stat1[256];
__device__ float d_stat2[512];
__device__ float d_stat3[256];
__device__ float d_a0[64],  d_c0[64];
__device__ float d_a1[128], d_c1[128];
__device__ float d_a2[256], d_c2[256];
__device__ float d_a3[128], d_c3[128];

// ---------------- packed f32x2 helpers ----------------
__device__ __forceinline__ unsigned long long pk2(float lo, float hi){
  unsigned long long r; asm("mov.b64 %0, {%1, %2};" : "=l"(r) : "f"(lo), "f"(hi)); return r;
}
__device__ __forceinline__ void fma2(unsigned long long& d, unsigned long long a, unsigned long long b){
  asm("fma.rn.f32x2 %0, %1, %2, %0;" : "+l"(d) : "l"(a), "l"(b));
}
__device__ __forceinline__ void unpk(unsigned long long v, float& lo, float& hi){
  asm("mov.b64 {%0, %1}, %2;" : "=f"(lo), "=f"(hi) : "l"(v));
}

// =====================================================================
// Strided conv k=4 s=2 p=1.
// =====================================================================
template<int IC, int OC, int IH, int IW, int OH, int OW, int OUT_CB,
         int TILE_OY, int CO_BLK, int CI_CHUNK, int NG_OX, int NG_CO,
         bool ACT_IN_LRELU, bool BIAS, bool TANH_OUT, bool REDUCE>
__global__ void __launch_bounds__(NG_CO*NG_OX*TILE_OY, 1536/(NG_CO*NG_OX*TILE_OY))
conv_s2_kernel(const float* __restrict__ in, const float* __restrict__ w,
               const float* __restrict__ bias,
               const float* __restrict__ a_in, const float* __restrict__ c_in,
               float* __restrict__ out, float* __restrict__ stat)
{
  constexpr int NT    = NG_CO * NG_OX * TILE_OY;
  constexpr int CO_T  = CO_BLK / NG_CO;
  constexpr int CO_P  = CO_T / 2;
  constexpr int ROWS  = 2*TILE_OY + 2;
  constexpr int COLSP = IW + 4;
  static_assert(OW / NG_OX == 8, "");

  __shared__ __align__(16) float sIn[CI_CHUNK][ROWS][COLSP];
  __shared__ __align__(16) unsigned long long sWp[CI_CHUNK][16][CO_BLK/2];
  __shared__ float sRed[2*CO_BLK];

  const int tid   = threadIdx.x;
  const int co_g  = tid % NG_CO;
  const int ox_g  = (tid / NG_CO) % NG_OX;
  const int oy_l  = tid / (NG_CO * NG_OX);
  const int co_base = blockIdx.y * CO_BLK;
  const int b     = blockIdx.z;
  const int oy0   = blockIdx.x * TILE_OY;
  const int iy0   = 2*oy0 - 1;
  const int co_t0 = co_g * CO_T;

  unsigned long long acc[8][CO_P];
  #pragma unroll
  for (int u=0;u<8;u++)
    #pragma unroll
    for (int j=0;j<CO_P;j++) acc[u][j] = 0ULL;

  for (int ci0 = 0; ci0 < IC; ci0 += CI_CHUNK) {
    for (int idx = tid; idx < CI_CHUNK*ROWS*COLSP; idx += NT) {
      int cc  = idx / (ROWS*COLSP);
      int rem = idx % (ROWS*COLSP);
      int r   = rem / COLSP, col = rem % COLSP;
      int iy  = iy0 + r, ix = col - 1;
      float v = 0.f;
      if (ix >= 0 && ix < IW && iy >= 0 && iy < IH) {
        v = in[((b*IC + ci0+cc)*IH + iy)*IW + ix];
        if constexpr (ACT_IN_LRELU) {
          float t = fmaf(a_in[ci0+cc], v, c_in[ci0+cc]);
          v = t > 0.f ? t : 0.2f*t;
        }
      }
      sIn[cc][r][col] = v;
    }
    for (int idx = tid; idx < CI_CHUNK*16*(CO_BLK/2); idx += NT) {
      int cc  = idx / (16*(CO_BLK/2));
      int rem = idx % (16*(CO_BLK/2));
      int k   = rem / (CO_BLK/2), pp = rem % (CO_BLK/2);
      int g = pp % NG_CO, j = pp / NG_CO;
      int co = co_base + g*CO_T + 2*j;
      float w0 = w[(co    *IC + ci0+cc)*16 + k];
      float w1 = w[((co+1)*IC + ci0+cc)*16 + k];
      sWp[cc][k][pp] = pk2(w0, w1);
    }
    __syncthreads();

    #pragma unroll
    for (int cc=0; cc<CI_CHUNK; cc++) {
      #pragma unroll
      for (int k=0;k<16;k++) {
        const int ky = k >> 2, kx = k & 3;
        unsigned long long wv[CO_P];
        #pragma unroll
        for (int j=0;j<CO_P;j++)
          wv[j] = sWp[cc][k][j*NG_CO + co_g];
        const float* rowp = &sIn[cc][2*oy_l + ky][0];
        #pragma unroll
        for (int u=0;u<8;u++) {
          float iv = rowp[2*(ox_g + NG_OX*u) + kx];
          unsigned long long pv = pk2(iv, iv);
          #pragma unroll
          for (int j=0;j<CO_P;j++) fma2(acc[u][j], pv, wv[j]);
        }
      }
    }
    __syncthreads();
  }

  if constexpr (REDUCE) {
    for (int i = tid; i < 2*CO_BLK; i += NT) sRed[i] = 0.f;
    __syncthreads();
  }

  const int oy = oy0 + oy_l;
  #pragma unroll
  for (int j=0;j<CO_P;j++){
    float v0[8], v1[8];
    #pragma unroll
    for (int u=0;u<8;u++) unpk(acc[u][j], v0[u], v1[u]);
    const int co = co_base + co_t0 + 2*j;
    if constexpr (BIAS) {
      float b0 = bias[co], b1 = bias[co+1];
      #pragma unroll
      for (int u=0;u<8;u++){ v0[u]+=b0; v1[u]+=b1; }
    }
    if constexpr (TANH_OUT) {
      #pragma unroll
      for (int u=0;u<8;u++){ v0[u]=tanhf(v0[u]); v1[u]=tanhf(v1[u]); }
    }
    float* p0 = &out[((b*OUT_CB + co  )*OH + oy)*OW];
    float* p1 = &out[((b*OUT_CB + co+1)*OH + oy)*OW];
    #pragma unroll
    for (int u=0;u<8;u++){
      p0[ox_g + NG_OX*u] = v0[u];
      p1[ox_g + NG_OX*u] = v1[u];
    }
    if constexpr (REDUCE) {
      float s0=0.f,q0=0.f,s1=0.f,q1=0.f;
      #pragma unroll
      for (int u=0;u<8;u++){ s0+=v0[u]; q0=fmaf(v0[u],v0[u],q0); s1+=v1[u]; q1=fmaf(v1[u],v1[u],q1); }
      int cl = co_t0 + 2*j;
      atomicAdd(&sRed[cl],            s0);
      atomicAdd(&sRed[CO_BLK+cl],     q0);
      atomicAdd(&sRed[cl+1],          s1);
      atomicAdd(&sRed[CO_BLK+cl+1],   q1);
    }
  }
  if constexpr (REDUCE) {
    __syncthreads();
    if (tid < 2*CO_BLK) {
      int cl = (tid < CO_BLK) ? tid : (tid - CO_BLK);
      int off = (tid < CO_BLK) ? 0 : OC;
      atomicAdd(&stat[off + co_base + cl], sRed[tid]);
    }
  }
}

// =====================================================================
// Transposed conv k=4 s=2 p=1 via parity decomposition.
// =====================================================================
template<int IC, int OC, int IH, int IW, int OUT_CB,
         int TILE_M, int CO_BLK, int CI_CHUNK, int NG_N, int NG_CO,
         bool ACT_IN_RELU, bool REDUCE>
__global__ void __launch_bounds__(NG_N*NG_CO*TILE_M, 1536/(NG_N*NG_CO*TILE_M))
deconv_kernel(const float* __restrict__ in, const float* __restrict__ w,
              const float* __restrict__ a_in, const float* __restrict__ c_in,
              float* __restrict__ out, float* __restrict__ stat)
{
  constexpr int NT    = NG_N * NG_CO * TILE_M;
  constexpr int CO_T  = CO_BLK / NG_CO;
  constexpr int CO_P  = CO_T / 2;
  constexpr int ROWS  = TILE_M + 1;
  constexpr int COLSP = IW + 2;
  constexpr int NCO_G = OC / CO_BLK;
  static_assert(IW / NG_N == 8, "");

  __shared__ __align__(16) float sIn[CI_CHUNK][ROWS][COLSP];
  __shared__ __align__(16) unsigned long long sWp[CI_CHUNK][4][CO_BLK/2];
  __shared__ float sRed[2*CO_BLK];

  const int tid    = threadIdx.x;
  const int n_g    = tid % NG_N;
  const int co_g   = (tid / NG_N) % NG_CO;
  const int m_l    = tid / (NG_N * NG_CO);
  const int co_grp = blockIdx.x % NCO_G;
  const int m_tile = blockIdx.x / NCO_G;
  const int ry     = blockIdx.y >> 1, rx = blockIdx.y & 1;
  const int b      = blockIdx.z;
  const int m0     = m_tile * TILE_M;
  const int co_base= co_grp * CO_BLK;
  const int n0     = n_g * 8;
  const int co_t0  = co_g * CO_T;

  unsigned long long acc[8][CO_P];
  #pragma unroll
  for (int u=0;u<8;u++)
    #pragma unroll
    for (int j=0;j<CO_P;j++) acc[u][j] = 0ULL;

  for (int ci0 = 0; ci0 < IC; ci0 += CI_CHUNK) {
    for (int idx = tid; idx < CI_CHUNK*ROWS*COLSP; idx += NT) {
      int cc  = idx / (ROWS*COLSP);
      int rem = idx % (ROWS*COLSP);
      int r   = rem / COLSP, col = rem % COLSP;
      int gy  = m0 + ry - 1 + r;
      int gx  = rx - 1 + col;
      float v = 0.f;
      if (gy >= 0 && gy < IH && gx >= 0 && gx < IW) {
        v = in[((b*IC + ci0+cc)*IH + gy)*IW + gx];
        if constexpr (ACT_IN_RELU)
          v = fmaxf(fmaf(a_in[ci0+cc], v, c_in[ci0+cc]), 0.f);
      }
      sIn[cc][r][col] = v;
    }
    for (int idx = tid; idx < CI_CHUNK*4*(CO_BLK/2); idx += NT) {
      int cc  = idx / (4*(CO_BLK/2));
      int rem = idx % (4*(CO_BLK/2));
      int t4  = rem / (CO_BLK/2), pp = rem % (CO_BLK/2);
      int g = pp % NG_CO, j = pp / NG_CO;
      int dd = t4 >> 1, ee = t4 & 1;
      int co = co_base + g*CO_T + 2*j;
      int koff = (3-ry-2*dd)*4 + (3-rx-2*ee);
      float w0 = w[((ci0+cc)*OC + co  )*16 + koff];
      float w1 = w[((ci0+cc)*OC + co+1)*16 + koff];
      sWp[cc][t4][pp] = pk2(w0, w1);
    }
    __syncthreads();

    #pragma unroll
    for (int cc=0; cc<CI_CHUNK; cc++) {
      #pragma unroll
      for (int t4=0;t4<4;t4++) {
        const int dd = t4 >> 1, ee = t4 & 1;
        unsigned long long wv[CO_P];
        #pragma unroll
        for (int j=0;j<CO_P;j++)
          wv[j] = sWp[cc][t4][j*NG_CO + co_g];
        const float* rowp = &sIn[cc][m_l + dd][0];
        #pragma unroll
        for (int u=0;u<8;u++) {
          float iv = rowp[n0 + u + ee];
          unsigned long long pv = pk2(iv, iv);
          #pragma unroll
          for (int j=0;j<CO_P;j++) fma2(acc[u][j], pv, wv[j]);
        }
      }
    }
    __syncthreads();
  }

  if constexpr (REDUCE) {
    for (int i = tid; i < 2*CO_BLK; i += NT) sRed[i] = 0.f;
    __syncthreads();
  }

  const int oy = 2*(m0 + m_l) + ry;
  const int OW2 = 2*IW, OH2 = 2*IH;
  #pragma unroll
  for (int j=0;j<CO_P;j++){
    const int co = co_base + co_t0 + 2*j;
    float* r0 = &out[((b*OUT_CB + co  )*OH2 + oy)*OW2 + rx];
    float* r1 = &out[((b*OUT_CB + co+1)*OH2 + oy)*OW2 + rx];
    float s0=0.f,q0=0.f,s1=0.f,q1=0.f;
    #pragma unroll
    for (int u=0;u<8;u++){
      float v0, v1; unpk(acc[u][j], v0, v1);
      r0[2*(n0+u)] = v0;
      r1[2*(n0+u)] = v1;
      if constexpr (REDUCE) { s0+=v0; q0=fmaf(v0,v0,q0); s1+=v1; q1=fmaf(v1,v1,q1); }
    }
    if constexpr (REDUCE) {
      int cl = co_t0 + 2*j;
      atomicAdd(&sRed[cl],          s0);
      atomicAdd(&sRed[CO_BLK+cl],   q0);
      atomicAdd(&sRed[cl+1],        s1);
      atomicAdd(&sRed[CO_BLK+cl+1], q1);
    }
  }
  if constexpr (REDUCE) {
    __syncthreads();
    if (tid < 2*CO_BLK) {
      int cl = (tid < CO_BLK) ? tid : (tid - CO_BLK);
      int off = (tid < CO_BLK) ? 0 : OC;
      atomicAdd(&stat[off + co_base + cl], sRed[tid]);
    }
  }
}

// =====================================================================
// Final deconv 128->3 with bias + tanh (scalar accumulators)
// =====================================================================
__global__ void __launch_bounds__(128, 8)
deconv2_kernel(const float* __restrict__ in, const float* __restrict__ w,
               const float* __restrict__ bias,
               const float* __restrict__ a_in, const float* __restrict__ c_in,
               float* __restrict__ out)
{
  constexpr int IC=128, IH=64, IW=64, TILE_M=16, CI=4, NG_N=8;
  constexpr int NT=128, ROWS=TILE_M+1, COLSP=IW+2;
  __shared__ float sIn[CI][ROWS][COLSP];
  __shared__ float sW[CI][4][4];

  const int tid = threadIdx.x;
  const int n_g = tid % NG_N;
  const int m_l = tid / NG_N;
  const int m0  = blockIdx.x * TILE_M;
  const int ry  = blockIdx.y >> 1, rx = blockIdx.y & 1;
  const int b   = blockIdx.z;
  const int n0  = n_g * 8;

  float acc[3][8];
  #pragma unroll
  for (int co=0;co<3;co++)
    #pragma unroll
    for (int u=0;u<8;u++) acc[co][u] = 0.f;

  for (int ci0 = 0; ci0 < IC; ci0 += CI) {
    for (int idx = tid; idx < CI*ROWS*COLSP; idx += NT) {
      int cc  = idx / (ROWS*COLSP);
      int rem = idx % (ROWS*COLSP);
      int r   = rem / COLSP, col = rem % COLSP;
      int gy  = m0 + ry - 1 + r;
      int gx  = rx - 1 + col;
      float v = 0.f;
      if (gy >= 0 && gy < IH && gx >= 0 && gx < IW)
        v = fmaxf(fmaf(a_in[ci0+cc], in[((b*IC + ci0+cc)*IH + gy)*IW + gx], c_in[ci0+cc]), 0.f);
      sIn[cc][r][col] = v;
    }
    if (tid < 48) {
      int cc = tid / 12, t4 = (tid / 3) % 4, co = tid % 3;
      int dd = t4 >> 1, ee = t4 & 1;
      sW[cc][t4][co] = w[((ci0+cc)*3 + co)*16 + (3-ry-2*dd)*4 + (3-rx-2*ee)];
    }
    __syncthreads();

    #pragma unroll
    for (int cc=0; cc<CI; cc++) {
      #pragma unroll
      for (int t4=0;t4<4;t4++) {
        const int dd = t4 >> 1, ee = t4 & 1;
        float w0 = sW[cc][t4][0], w1 = sW[cc][t4][1], w2 = sW[cc][t4][2];
        const float* rowp = &sIn[cc][m_l + dd][0];
        #pragma unroll
        for (int u=0;u<8;u++) {
          float iv = rowp[n0 + u + ee];
          acc[0][u] = fmaf(iv, w0, acc[0][u]);
          acc[1][u] = fmaf(iv, w1, acc[1][u]);
          acc[2][u] = fmaf(iv, w2, acc[2][u]);
        }
      }
    }
    __syncthreads();
  }

  const int oy = 2*(m0 + m_l) + ry;
  #pragma unroll
  for (int co=0;co<3;co++){
    float bb = bias[co];
    float* rp = &out[((b*3 + co)*128 + oy)*128 + rx];
    #pragma unroll
    for (int u=0;u<8;u++)
      rp[2*(n0+u)] = tanhf(acc[co][u] + bb);
  }
}

// =====================================================================
__global__ void finalize_kernel(const float* __restrict__ stat, const float* __restrict__ g,
                                const float* __restrict__ be,
                                float* __restrict__ a, float* __restrict__ cv,
                                int C, float invN)
{
  int c = threadIdx.x + blockIdx.x*blockDim.x;
  if (c >= C) return;
  float mean = stat[c] * invN;
  float var  = stat[C + c] * invN - mean*mean;
  float av = g[c] * rsqrtf(var + 1e-5f);
  a[c] = av;
  cv[c] = be[c] - mean * av;
}

__global__ void zero_kernel(float* s0, float* s1, float* s2, float* s3)
{
  int t = threadIdx.x;
  if (t < 128) s0[t] = 0.f;
  if (t < 256) s1[t] = 0.f;
  if (t < 512) s2[t] = 0.f;
  if (t < 256) s3[t] = 0.f;
}

__global__ void pack_kernel(const float* __restrict__ Zl, const float* __restrict__ Zg,
                            float* __restrict__ Zbuf)
{
  int idx = blockIdx.x * 256 + threadIdx.x;
  const int nl = 64*32*256;
  if (idx < nl) {
    int b = idx / (32*256); int r = idx % (32*256);
    Zbuf[(b*168 + 64)*256 + r] = Zl[idx];
  }
  const int ng = 64*64*256;
  if (idx < ng) {
    int b = idx / (64*256); int r = idx % (64*256);
    Zbuf[(b*168 + 96)*256 + r] = Zg[idx];
  }
}

__global__ void wave_kernel(const float* __restrict__ Zg, const float* __restrict__ phi,
                            const float* __restrict__ lW, const float* __restrict__ lb,
                            const float* __restrict__ l1W, const float* __restrict__ l1b,
                            const float* __restrict__ l2W, const float* __restrict__ l2b,
                            float* __restrict__ Zbuf)
{
  const int b = blockIdx.x;
  const int t = threadIdx.x;  // 64
  __shared__ float zg[64], x[64], K[16];
  zg[t] = Zg[(b*64 + t)*256];
  __syncthreads();
  float acc = lb[t];
  #pragma unroll 8
  for (int g = 0; g < 64; g++) acc = fmaf(zg[g], lW[t*64+g], acc);
  x[t] = fmaxf(acc, 0.f);
  __syncthreads();
  if (t < 16) {
    int p = t & 7;
    const float* W  = (t < 8) ? l1W : l2W;
    const float* bb = (t < 8) ? l1b : l2b;
    float k = bb[p];
    #pragma unroll 8
    for (int h = 0; h < 64; h++) k = fmaf(x[h], W[p*64+h], k);
    K[t] = k;
  }
  __syncthreads();
  for (int idx = t; idx < 8*256; idx += 64) {
    int p = idx >> 8; int ij = idx & 255; int i = ij >> 4; int j = ij & 15;
    float wv = K[p]*(float)i + K[p+8]*(float)j + phi[b*8+p]*TWO_PI_F;
    Zbuf[(b*168 + 160 + p)*256 + ij] = sinf(wv);
  }
}

// =====================================================================
extern "C" void kernel_launch(void* const* d_in, const int* in_sizes, int n_in,
                              void* d_out, int out_size)
{
  const float* Zl   = (const float*)d_in[0];
  const float* Zg   = (const float*)d_in[1];
  const float* imgs = (const float*)d_in[2];
  const float* phi  = (const float*)d_in[3];
  const float* lW   = (const float*)d_in[4];
  const float* lb   = (const float*)d_in[5];
  const float* l1W  = (const float*)d_in[6];
  const float* l1b  = (const float*)d_in[7];
  const float* l2W  = (const float*)d_in[8];
  const float* l2b  = (const float*)d_in[9];
  const float* cw0  = (const float*)d_in[10];
  const float* cg0  = (const float*)d_in[12];
  const float* cbe0 = (const float*)d_in[13];
  const float* cw1  = (const float*)d_in[14];
  const float* cg1  = (const float*)d_in[16];
  const float* cbe1 = (const float*)d_in[17];
  const float* cw2  = (const float*)d_in[18];
  const float* cb2  = (const float*)d_in[19];
  const float* gw0  = (const float*)d_in[20];
  const float* gg0  = (const float*)d_in[22];
  const float* gbe0 = (const float*)d_in[23];
  const float* gw1  = (const float*)d_in[24];
  const float* gg1  = (const float*)d_in[26];
  const float* gbe1 = (const float*)d_in[27];
  const float* gw2  = (const float*)d_in[28];
  const float* gb2  = (const float*)d_in[29];
  float* out = (float*)d_out;

  float *h0,*h1,*Zb,*g0,*g1;
  float *s0,*s1,*s2,*s3;
  float *a0,*c0,*a1,*c1,*a2,*c2,*a3,*c3;
  cudaGetSymbolAddress((void**)&h0, d_h0);
  cudaGetSymbolAddress((void**)&h1, d_h1);
  cudaGetSymbolAddress((void**)&Zb, d_Zbuf);
  cudaGetSymbolAddress((void**)&g0, d_g0);
  cudaGetSymbolAddress((void**)&g1, d_g1);
  cudaGetSymbolAddress((void**)&s0, d_stat0);
  cudaGetSymbolAddress((void**)&s1, d_stat1);
  cudaGetSymbolAddress((void**)&s2, d_stat2);
  cudaGetSymbolAddress((void**)&s3, d_stat3);
  cudaGetSymbolAddress((void**)&a0, d_a0); cudaGetSymbolAddress((void**)&c0, d_c0);
  cudaGetSymbolAddress((void**)&a1, d_a1); cudaGetSymbolAddress((void**)&c1, d_c1);
  cudaGetSymbolAddress((void**)&a2, d_a2); cudaGetSymbolAddress((void**)&c2, d_c2);
  cudaGetSymbolAddress((void**)&a3, d_a3); cudaGetSymbolAddress((void**)&c3, d_c3);

  // Max shared-memory carveout so multiple blocks co-reside (occupancy fix).
  auto k_conv0 = conv_s2_kernel<3,64,128,128,64,64, 64, 4,64,3,8,8, false,false,false,true>;
  auto k_conv1 = conv_s2_kernel<64,128,64,64,32,32, 128, 8,64,4,4,8, true,false,false,true>;
  auto k_conv2 = conv_s2_kernel<128,64,32,32,16,16, 168, 8,64,4,2,16, true,true,true,false>;
  auto k_dec0  = deconv_kernel<168,256,16,16, 256, 8,128,8,2,16, false,true>;
  auto k_dec1  = deconv_kernel<256,128,32,32, 128, 8,128,8,4,16, true,true>;
  static bool attr_done = false;
  if (!attr_done) {
    cudaFuncSetAttribute((const void*)k_conv0, cudaFuncAttributePreferredSharedMemoryCarveout, 100);
    cudaFuncSetAttribute((const void*)k_conv1, cudaFuncAttributePreferredSharedMemoryCarveout, 100);
    cudaFuncSetAttribute((const void*)k_conv2, cudaFuncAttributePreferredSharedMemoryCarveout, 100);
    cudaFuncSetAttribute((const void*)k_dec0,  cudaFuncAttributePreferredSharedMemoryCarveout, 100);
    cudaFuncSetAttribute((const void*)k_dec1,  cudaFuncAttributePreferredSharedMemoryCarveout, 100);
    cudaFuncSetAttribute((const void*)deconv2_kernel, cudaFuncAttributePreferredSharedMemoryCarveout, 100);
    attr_done = true;
  }

  zero_kernel<<<1,512>>>(s0, s1, s2, s3);
  pack_kernel<<<4096,256>>>(Zl, Zg, Zb);
  wave_kernel<<<64,64>>>(Zg, phi, lW, lb, l1W, l1b, l2W, l2b, Zb);

  // encoder (stats fused)
  k_conv0<<<dim3(16,1,64),256>>>(imgs, cw0, nullptr, nullptr, nullptr, h0, s0);
  finalize_kernel<<<1,64>>>(s0, cg0, cbe0, a0, c0, 64, 1.f/(64.f*4096.f));
  k_conv1<<<dim3(4,2,64),256>>>(h0, cw1, nullptr, a0, c0, h1, s1);
  finalize_kernel<<<1,128>>>(s1, cg1, cbe1, a1, c1, 128, 1.f/(64.f*1024.f));
  k_conv2<<<dim3(2,1,64),256>>>(h1, cw2, cb2, a1, c1, Zb, nullptr);

  // generator (stats fused)
  k_dec0<<<dim3(4,4,64),256>>>(Zb, gw0, nullptr, nullptr, g0, s2);
  finalize_kernel<<<1,256>>>(s2, gg0, gbe0, a2, c2, 256, 1.f/(64.f*1024.f));
  k_dec1<<<dim3(4,4,64),512>>>(g0, gw1, a2, c2, g1, s3);
  finalize_kernel<<<1,128>>>(s3, gg1, gbe1, a3, c3, 128, 1.f/(64.f*4096.f));
  deconv2_kernel<<<dim3(4,4,64),128>>>(g1, gw2, gb2, a3, c3, out);
}

// round 7
// speedup vs baseline: 6.9628x; 6.9628x over previous
#include <cuda_runtime.h>
#include <math.h>

#define TWO_PI_F 6.2831853071795864769f

// ---------------- device scratch ----------------
__device__ float d_h0[64*64*64*64];
__device__ float d_h1[64*128*32*32];
__device__ float d_Zbuf[64*168*16*16];
__device__ float d_g0[64*256*32*32];
__device__ float d_g1[64*128*64*64];
__device__ float d_stat0[128];
__device__ float d_stat1[256];
__device__ float d_stat2[512];
__device__ float d_stat3[256];
__device__ float d_a0[64],  d_c0[64];
__device__ float d_a1[128], d_c1[128];
__device__ float d_a2[256], d_c2[256];
__device__ float d_a3[128], d_c3[128];

// ---------------- packed f32x2 helpers ----------------
__device__ __forceinline__ unsigned long long pk2(float lo, float hi){
  unsigned long long r; asm("mov.b64 %0, {%1, %2};" : "=l"(r) : "f"(lo), "f"(hi)); return r;
}
__device__ __forceinline__ void fma2(unsigned long long& d, unsigned long long a, unsigned long long b){
  asm("fma.rn.f32x2 %0, %1, %2, %0;" : "+l"(d) : "l"(a), "l"(b));
}
__device__ __forceinline__ void unpk(unsigned long long v, float& lo, float& hi){
  asm("mov.b64 {%0, %1}, %2;" : "=f"(lo), "=f"(hi) : "l"(v));
}

// =====================================================================
// Strided conv k=4 s=2 p=1. Per-thread tile: U ox x CO_T co (pairs).
// U*CO_P = 16 packed accumulators = 32 regs -> 3 blocks/SM.
// =====================================================================
template<int IC, int OC, int IH, int IW, int OH, int OW, int OUT_CB,
         int TILE_OY, int CO_BLK, int CI_CHUNK, int NG_OX, int NG_CO, int U,
         bool ACT_IN_LRELU, bool BIAS, bool TANH_OUT, bool REDUCE>
__global__ void __launch_bounds__(NG_CO*NG_OX*TILE_OY, 768/(NG_CO*NG_OX*TILE_OY))
conv_s2_kernel(const float* __restrict__ in, const float* __restrict__ w,
               const float* __restrict__ bias,
               const float* __restrict__ a_in, const float* __restrict__ c_in,
               float* __restrict__ out, float* __restrict__ stat)
{
  constexpr int NT    = NG_CO * NG_OX * TILE_OY;
  constexpr int CO_T  = CO_BLK / NG_CO;
  constexpr int CO_P  = CO_T / 2;
  constexpr int ROWS  = 2*TILE_OY + 2;
  constexpr int COLSP = IW + 4;
  static_assert(OW == NG_OX*U, "");

  __shared__ __align__(16) float sIn[CI_CHUNK][ROWS][COLSP];
  __shared__ __align__(16) float sW [CI_CHUNK][16][CO_BLK];
  __shared__ float sRed[2*CO_BLK];

  const int tid   = threadIdx.x;
  const int co_g  = tid % NG_CO;
  const int ox_g  = (tid / NG_CO) % NG_OX;
  const int oy_l  = tid / (NG_CO * NG_OX);
  const int co_base = blockIdx.y * CO_BLK;
  const int b     = blockIdx.z;
  const int oy0   = blockIdx.x * TILE_OY;
  const int iy0   = 2*oy0 - 1;
  const int ox0   = ox_g * U;
  const int co_t0 = co_g * CO_T;

  unsigned long long acc[U][CO_P];
  #pragma unroll
  for (int u=0;u<U;u++)
    #pragma unroll
    for (int j=0;j<CO_P;j++) acc[u][j] = 0ULL;

  for (int ci0 = 0; ci0 < IC; ci0 += CI_CHUNK) {
    for (int idx = tid; idx < CI_CHUNK*ROWS*COLSP; idx += NT) {
      int cc  = idx / (ROWS*COLSP);
      int rem = idx % (ROWS*COLSP);
      int r   = rem / COLSP, col = rem % COLSP;
      int iy  = iy0 + r, ix = col - 1;
      float v = 0.f;
      if (ix >= 0 && ix < IW && iy >= 0 && iy < IH) {
        v = in[((b*IC + ci0+cc)*IH + iy)*IW + ix];
        if constexpr (ACT_IN_LRELU) {
          float t = fmaf(a_in[ci0+cc], v, c_in[ci0+cc]);
          v = t > 0.f ? t : 0.2f*t;
        }
      }
      sIn[cc][r][col] = v;
    }
    for (int idx = tid; idx < CI_CHUNK*16*CO_BLK; idx += NT) {
      int cc  = idx / (16*CO_BLK);
      int rem = idx % (16*CO_BLK);
      int k   = rem / CO_BLK, co = rem % CO_BLK;
      sW[cc][k][co] = w[((co_base+co)*IC + ci0+cc)*16 + k];
    }
    __syncthreads();

    #pragma unroll
    for (int cc=0; cc<CI_CHUNK; cc++) {
      #pragma unroll
      for (int k=0;k<16;k++) {
        const int ky = k >> 2, kx = k & 3;
        unsigned long long wv[CO_P];
        #pragma unroll
        for (int j=0;j<CO_P;j++)
          wv[j] = *reinterpret_cast<const unsigned long long*>(&sW[cc][k][co_t0 + 2*j]);
        const float* rowp = &sIn[cc][2*oy_l + ky][0];
        #pragma unroll
        for (int u=0;u<U;u++) {
          float iv = rowp[2*(ox0+u) + kx];
          unsigned long long pv = pk2(iv, iv);
          #pragma unroll
          for (int j=0;j<CO_P;j++) fma2(acc[u][j], pv, wv[j]);
        }
      }
    }
    __syncthreads();
  }

  if constexpr (REDUCE) {
    for (int i = tid; i < 2*CO_BLK; i += NT) sRed[i] = 0.f;
    __syncthreads();
  }

  const int oy = oy0 + oy_l;
  #pragma unroll
  for (int j=0;j<CO_P;j++){
    float v0[U], v1[U];
    #pragma unroll
    for (int u=0;u<U;u++) unpk(acc[u][j], v0[u], v1[u]);
    const int co = co_base + co_t0 + 2*j;
    if constexpr (BIAS) {
      float b0 = bias[co], b1 = bias[co+1];
      #pragma unroll
      for (int u=0;u<U;u++){ v0[u]+=b0; v1[u]+=b1; }
    }
    if constexpr (TANH_OUT) {
      #pragma unroll
      for (int u=0;u<U;u++){ v0[u]=tanhf(v0[u]); v1[u]=tanhf(v1[u]); }
    }
    float* p0 = &out[((b*OUT_CB + co  )*OH + oy)*OW + ox0];
    float* p1 = &out[((b*OUT_CB + co+1)*OH + oy)*OW + ox0];
    if constexpr (U == 4) {
      *reinterpret_cast<float4*>(p0) = make_float4(v0[0],v0[1],v0[2],v0[3]);
      *reinterpret_cast<float4*>(p1) = make_float4(v1[0],v1[1],v1[2],v1[3]);
    } else {
      #pragma unroll
      for (int u=0;u<U;u++){ p0[u]=v0[u]; p1[u]=v1[u]; }
    }
    if constexpr (REDUCE) {
      float s0=0.f,q0=0.f,s1=0.f,q1=0.f;
      #pragma unroll
      for (int u=0;u<U;u++){ s0+=v0[u]; q0=fmaf(v0[u],v0[u],q0); s1+=v1[u]; q1=fmaf(v1[u],v1[u],q1); }
      int cl = co_t0 + 2*j;
      atomicAdd(&sRed[cl],          s0);
      atomicAdd(&sRed[CO_BLK+cl],   q0);
      atomicAdd(&sRed[cl+1],        s1);
      atomicAdd(&sRed[CO_BLK+cl+1], q1);
    }
  }
  if constexpr (REDUCE) {
    __syncthreads();
    if (tid < 2*CO_BLK) {
      int cl = (tid < CO_BLK) ? tid : (tid - CO_BLK);
      int off = (tid < CO_BLK) ? 0 : OC;
      atomicAdd(&stat[off + co_base + cl], sRed[tid]);
    }
  }
}

// =====================================================================
// Transposed conv k=4 s=2 p=1 via parity decomposition. Per-thread:
// U n-positions x CO_T co (pairs), U*CO_P = 16.
// =====================================================================
template<int IC, int OC, int IH, int IW, int OUT_CB,
         int TILE_M, int CO_BLK, int CI_CHUNK, int NG_N, int NG_CO, int U,
         bool ACT_IN_RELU, bool REDUCE>
__global__ void __launch_bounds__(NG_N*NG_CO*TILE_M, 768/(NG_N*NG_CO*TILE_M))
deconv_kernel(const float* __restrict__ in, const float* __restrict__ w,
              const float* __restrict__ a_in, const float* __restrict__ c_in,
              float* __restrict__ out, float* __restrict__ stat)
{
  constexpr int NT    = NG_N * NG_CO * TILE_M;
  constexpr int CO_T  = CO_BLK / NG_CO;
  constexpr int CO_P  = CO_T / 2;
  constexpr int ROWS  = TILE_M + 1;
  constexpr int COLSP = IW + 2;
  constexpr int NCO_G = OC / CO_BLK;
  static_assert(IW == NG_N*U, "");

  __shared__ __align__(16) float sIn[CI_CHUNK][ROWS][COLSP];
  __shared__ __align__(16) float sW [CI_CHUNK][4][CO_BLK];
  __shared__ float sRed[2*CO_BLK];

  const int tid    = threadIdx.x;
  const int n_g    = tid % NG_N;
  const int co_g   = (tid / NG_N) % NG_CO;
  const int m_l    = tid / (NG_N * NG_CO);
  const int co_grp = blockIdx.x % NCO_G;
  const int m_tile = blockIdx.x / NCO_G;
  const int ry     = blockIdx.y >> 1, rx = blockIdx.y & 1;
  const int b      = blockIdx.z;
  const int m0     = m_tile * TILE_M;
  const int co_base= co_grp * CO_BLK;
  const int n0     = n_g * U;
  const int co_t0  = co_g * CO_T;

  unsigned long long acc[U][CO_P];
  #pragma unroll
  for (int u=0;u<U;u++)
    #pragma unroll
    for (int j=0;j<CO_P;j++) acc[u][j] = 0ULL;

  for (int ci0 = 0; ci0 < IC; ci0 += CI_CHUNK) {
    for (int idx = tid; idx < CI_CHUNK*ROWS*COLSP; idx += NT) {
      int cc  = idx / (ROWS*COLSP);
      int rem = idx % (ROWS*COLSP);
      int r   = rem / COLSP, col = rem % COLSP;
      int gy  = m0 + ry - 1 + r;
      int gx  = rx - 1 + col;
      float v = 0.f;
      if (gy >= 0 && gy < IH && gx >= 0 && gx < IW) {
        v = in[((b*IC + ci0+cc)*IH + gy)*IW + gx];
        if constexpr (ACT_IN_RELU)
          v = fmaxf(fmaf(a_in[ci0+cc], v, c_in[ci0+cc]), 0.f);
      }
      sIn[cc][r][col] = v;
    }
    for (int idx = tid; idx < CI_CHUNK*4*CO_BLK; idx += NT) {
      int cc  = idx / (4*CO_BLK);
      int rem = idx % (4*CO_BLK);
      int t4  = rem / CO_BLK, co = rem % CO_BLK;
      int dd = t4 >> 1, ee = t4 & 1;
      sW[cc][t4][co] = w[((ci0+cc)*OC + co_base+co)*16 + (3-ry-2*dd)*4 + (3-rx-2*ee)];
    }
    __syncthreads();

    #pragma unroll
    for (int cc=0; cc<CI_CHUNK; cc++) {
      #pragma unroll
      for (int t4=0;t4<4;t4++) {
        const int dd = t4 >> 1, ee = t4 & 1;
        unsigned long long wv[CO_P];
        #pragma unroll
        for (int j=0;j<CO_P;j++)
          wv[j] = *reinterpret_cast<const unsigned long long*>(&sW[cc][t4][co_t0 + 2*j]);
        const float* rowp = &sIn[cc][m_l + dd][0];
        #pragma unroll
        for (int u=0;u<U;u++) {
          float iv = rowp[n0 + u + ee];
          unsigned long long pv = pk2(iv, iv);
          #pragma unroll
          for (int j=0;j<CO_P;j++) fma2(acc[u][j], pv, wv[j]);
        }
      }
    }
    __syncthreads();
  }

  if constexpr (REDUCE) {
    for (int i = tid; i < 2*CO_BLK; i += NT) sRed[i] = 0.f;
    __syncthreads();
  }

  const int oy = 2*(m0 + m_l) + ry;
  const int OW2 = 2*IW, OH2 = 2*IH;
  #pragma unroll
  for (int j=0;j<CO_P;j++){
    const int co = co_base + co_t0 + 2*j;
    float* r0 = &out[((b*OUT_CB + co  )*OH2 + oy)*OW2 + rx];
    float* r1 = &out[((b*OUT_CB + co+1)*OH2 + oy)*OW2 + rx];
    float s0=0.f,q0=0.f,s1=0.f,q1=0.f;
    #pragma unroll
    for (int u=0;u<U;u++){
      float v0, v1; unpk(acc[u][j], v0, v1);
      r0[2*(n0+u)] = v0;
      r1[2*(n0+u)] = v1;
      if constexpr (REDUCE) { s0+=v0; q0=fmaf(v0,v0,q0); s1+=v1; q1=fmaf(v1,v1,q1); }
    }
    if constexpr (REDUCE) {
      int cl = co_t0 + 2*j;
      atomicAdd(&sRed[cl],          s0);
      atomicAdd(&sRed[CO_BLK+cl],   q0);
      atomicAdd(&sRed[cl+1],        s1);
      atomicAdd(&sRed[CO_BLK+cl+1], q1);
    }
  }
  if constexpr (REDUCE) {
    __syncthreads();
    if (tid < 2*CO_BLK) {
      int cl = (tid < CO_BLK) ? tid : (tid - CO_BLK);
      int off = (tid < CO_BLK) ? 0 : OC;
      atomicAdd(&stat[off + co_base + cl], sRed[tid]);
    }
  }
}

// =====================================================================
// Final deconv 128->3 with bias + tanh
// =====================================================================
__global__ void __launch_bounds__(128)
deconv2_kernel(const float* __restrict__ in, const float* __restrict__ w,
               const float* __restrict__ bias,
               const float* __restrict__ a_in, const float* __restrict__ c_in,
               float* __restrict__ out)
{
  constexpr int IC=128, IH=64, IW=64, TILE_M=16, CI=4, NG_N=8;
  constexpr int NT=128, ROWS=TILE_M+1, COLSP=IW+2;
  __shared__ float sIn[CI][ROWS][COLSP];
  __shared__ float sW[CI][4][4];

  const int tid = threadIdx.x;
  const int n_g = tid % NG_N;
  const int m_l = tid / NG_N;
  const int m0  = blockIdx.x * TILE_M;
  const int ry  = blockIdx.y >> 1, rx = blockIdx.y & 1;
  const int b   = blockIdx.z;
  const int n0  = n_g * 8;

  float acc[3][8];
  #pragma unroll
  for (int co=0;co<3;co++)
    #pragma unroll
    for (int u=0;u<8;u++) acc[co][u] = 0.f;

  for (int ci0 = 0; ci0 < IC; ci0 += CI) {
    for (int idx = tid; idx < CI*ROWS*COLSP; idx += NT) {
      int cc  = idx / (ROWS*COLSP);
      int rem = idx % (ROWS*COLSP);
      int r   = rem / COLSP, col = rem % COLSP;
      int gy  = m0 + ry - 1 + r;
      int gx  = rx - 1 + col;
      float v = 0.f;
      if (gy >= 0 && gy < IH && gx >= 0 && gx < IW)
        v = fmaxf(fmaf(a_in[ci0+cc], in[((b*IC + ci0+cc)*IH + gy)*IW + gx], c_in[ci0+cc]), 0.f);
      sIn[cc][r][col] = v;
    }
    if (tid < 48) {
      int cc = tid / 12, t4 = (tid / 3) % 4, co = tid % 3;
      int dd = t4 >> 1, ee = t4 & 1;
      sW[cc][t4][co] = w[((ci0+cc)*3 + co)*16 + (3-ry-2*dd)*4 + (3-rx-2*ee)];
    }
    __syncthreads();

    #pragma unroll
    for (int cc=0; cc<CI; cc++) {
      #pragma unroll
      for (int t4=0;t4<4;t4++) {
        const int dd = t4 >> 1, ee = t4 & 1;
        float w0 = sW[cc][t4][0], w1 = sW[cc][t4][1], w2 = sW[cc][t4][2];
        const float* rowp = &sIn[cc][m_l + dd][0];
        #pragma unroll
        for (int u=0;u<8;u++) {
          float iv = rowp[n0 + u + ee];
          acc[0][u] = fmaf(iv, w0, acc[0][u]);
          acc[1][u] = fmaf(iv, w1, acc[1][u]);
          acc[2][u] = fmaf(iv, w2, acc[2][u]);
        }
      }
    }
    __syncthreads();
  }

  const int oy = 2*(m0 + m_l) + ry;
  #pragma unroll
  for (int co=0;co<3;co++){
    float bb = bias[co];
    float* rp = &out[((b*3 + co)*128 + oy)*128 + rx];
    #pragma unroll
    for (int u=0;u<8;u++)
      rp[2*(n0+u)] = tanhf(acc[co][u] + bb);
  }
}

// =====================================================================
__global__ void finalize_kernel(const float* __restrict__ stat, const float* __restrict__ g,
                                const float* __restrict__ be,
                                float* __restrict__ a, float* __restrict__ cv,
                                int C, float invN)
{
  int c = threadIdx.x + blockIdx.x*blockDim.x;
  if (c >= C) return;
  float mean = stat[c] * invN;
  float var  = stat[C + c] * invN - mean*mean;
  float av = g[c] * rsqrtf(var + 1e-5f);
  a[c] = av;
  cv[c] = be[c] - mean * av;
}

__global__ void zero_kernel(float* s0, float* s1, float* s2, float* s3)
{
  int t = threadIdx.x;
  if (t < 128) s0[t] = 0.f;
  if (t < 256) s1[t] = 0.f;
  if (t < 512) s2[t] = 0.f;
  if (t < 256) s3[t] = 0.f;
}

__global__ void pack_kernel(const float* __restrict__ Zl, const float* __restrict__ Zg,
                            float* __restrict__ Zbuf)
{
  int idx = blockIdx.x * 256 + threadIdx.x;
  const int nl = 64*32*256;
  if (idx < nl) {
    int b = idx / (32*256); int r = idx % (32*256);
    Zbuf[(b*168 + 64)*256 + r] = Zl[idx];
  }
  const int ng = 64*64*256;
  if (idx < ng) {
    int b = idx / (64*256); int r = idx % (64*256);
    Zbuf[(b*168 + 96)*256 + r] = Zg[idx];
  }
}

__global__ void wave_kernel(const float* __restrict__ Zg, const float* __restrict__ phi,
                            const float* __restrict__ lW, const float* __restrict__ lb,
                            const float* __restrict__ l1W, const float* __restrict__ l1b,
                            const float* __restrict__ l2W, const float* __restrict__ l2b,
                            float* __restrict__ Zbuf)
{
  const int b = blockIdx.x;
  const int t = threadIdx.x;  // 64
  __shared__ float zg[64], x[64], K[16];
  zg[t] = Zg[(b*64 + t)*256];
  __syncthreads();
  float acc = lb[t];
  #pragma unroll 8
  for (int g = 0; g < 64; g++) acc = fmaf(zg[g], lW[t*64+g], acc);
  x[t] = fmaxf(acc, 0.f);
  __syncthreads();
  if (t < 16) {
    int p = t & 7;
    const float* W  = (t < 8) ? l1W : l2W;
    const float* bb = (t < 8) ? l1b : l2b;
    float k = bb[p];
    #pragma unroll 8
    for (int h = 0; h < 64; h++) k = fmaf(x[h], W[p*64+h], k);
    K[t] = k;
  }
  __syncthreads();
  for (int idx = t; idx < 8*256; idx += 64) {
    int p = idx >> 8; int ij = idx & 255; int i = ij >> 4; int j = ij & 15;
    float wv = K[p]*(float)i + K[p+8]*(float)j + phi[b*8+p]*TWO_PI_F;
    Zbuf[(b*168 + 160 + p)*256 + ij] = sinf(wv);
  }
}

// =====================================================================
extern "C" void kernel_launch(void* const* d_in, const int* in_sizes, int n_in,
                              void* d_out, int out_size)
{
  const float* Zl   = (const float*)d_in[0];
  const float* Zg   = (const float*)d_in[1];
  const float* imgs = (const float*)d_in[2];
  const float* phi  = (const float*)d_in[3];
  const float* lW   = (const float*)d_in[4];
  const float* lb   = (const float*)d_in[5];
  const float* l1W  = (const float*)d_in[6];
  const float* l1b  = (const float*)d_in[7];
  const float* l2W  = (const float*)d_in[8];
  const float* l2b  = (const float*)d_in[9];
  const float* cw0  = (const float*)d_in[10];
  const float* cg0  = (const float*)d_in[12];
  const float* cbe0 = (const float*)d_in[13];
  const float* cw1  = (const float*)d_in[14];
  const float* cg1  = (const float*)d_in[16];
  const float* cbe1 = (const float*)d_in[17];
  const float* cw2  = (const float*)d_in[18];
  const float* cb2  = (const float*)d_in[19];
  const float* gw0  = (const float*)d_in[20];
  const float* gg0  = (const float*)d_in[22];
  const float* gbe0 = (const float*)d_in[23];
  const float* gw1  = (const float*)d_in[24];
  const float* gg1  = (const float*)d_in[26];
  const float* gbe1 = (const float*)d_in[27];
  const float* gw2  = (const float*)d_in[28];
  const float* gb2  = (const float*)d_in[29];
  float* out = (float*)d_out;

  float *h0,*h1,*Zb,*g0,*g1;
  float *s0,*s1,*s2,*s3;
  float *a0,*c0,*a1,*c1,*a2,*c2,*a3,*c3;
  cudaGetSymbolAddress((void**)&h0, d_h0);
  cudaGetSymbolAddress((void**)&h1, d_h1);
  cudaGetSymbolAddress((void**)&Zb, d_Zbuf);
  cudaGetSymbolAddress((void**)&g0, d_g0);
  cudaGetSymbolAddress((void**)&g1, d_g1);
  cudaGetSymbolAddress((void**)&s0, d_stat0);
  cudaGetSymbolAddress((void**)&s1, d_stat1);
  cudaGetSymbolAddress((void**)&s2, d_stat2);
  cudaGetSymbolAddress((void**)&s3, d_stat3);
  cudaGetSymbolAddress((void**)&a0, d_a0); cudaGetSymbolAddress((void**)&c0, d_c0);
  cudaGetSymbolAddress((void**)&a1, d_a1); cudaGetSymbolAddress((void**)&c1, d_c1);
  cudaGetSymbolAddress((void**)&a2, d_a2); cudaGetSymbolAddress((void**)&c2, d_c2);
  cudaGetSymbolAddress((void**)&a3, d_a3); cudaGetSymbolAddress((void**)&c3, d_c3);

  // U*CO_P = 16 packed accumulators everywhere -> ~70 regs -> 3 blocks/SM
  auto k_conv0 = conv_s2_kernel<3,64,128,128,64,64, 64, 2,64,3, 16,8,4, false,false,false,true>;
  auto k_conv1 = conv_s2_kernel<64,128,64,64,32,32, 128, 4,64,4, 8,8,4, true,false,false,true>;
  auto k_conv2 = conv_s2_kernel<128,64,32,32,16,16, 168, 4,64,4, 4,16,4, true,true,true,false>;
  auto k_dec0  = deconv_kernel<168,256,16,16, 256, 4,128,8, 4,16,4, false,true>;
  auto k_dec1  = deconv_kernel<256,128,32,32, 128, 4,64,8, 4,16,8, true,true>;
  static bool attr_done = false;
  if (!attr_done) {
    cudaFuncSetAttribute((const void*)k_conv0, cudaFuncAttributePreferredSharedMemoryCarveout, 100);
    cudaFuncSetAttribute((const void*)k_conv1, cudaFuncAttributePreferredSharedMemoryCarveout, 100);
    cudaFuncSetAttribute((const void*)k_conv2, cudaFuncAttributePreferredSharedMemoryCarveout, 100);
    cudaFuncSetAttribute((const void*)k_dec0,  cudaFuncAttributePreferredSharedMemoryCarveout, 100);
    cudaFuncSetAttribute((const void*)k_dec1,  cudaFuncAttributePreferredSharedMemoryCarveout, 100);
    attr_done = true;
  }

  zero_kernel<<<1,512>>>(s0, s1, s2, s3);
  pack_kernel<<<4096,256>>>(Zl, Zg, Zb);
  wave_kernel<<<64,64>>>(Zg, phi, lW, lb, l1W, l1b, l2W, l2b, Zb);

  // encoder (stats fused)
  k_conv0<<<dim3(32,1,64),256>>>(imgs, cw0, nullptr, nullptr, nullptr, h0, s0);
  finalize_kernel<<<1,64>>>(s0, cg0, cbe0, a0, c0, 64, 1.f/(64.f*4096.f));
  k_conv1<<<dim3(8,2,64),256>>>(h0, cw1, nullptr, a0, c0, h1, s1);
  finalize_kernel<<<1,128>>>(s1, cg1, cbe1, a1, c1, 128, 1.f/(64.f*1024.f));
  k_conv2<<<dim3(4,1,64),256>>>(h1, cw2, cb2, a1, c1, Zb, nullptr);

  // generator (stats fused)
  k_dec0<<<dim3(8,4,64),256>>>(Zb, gw0, nullptr, nullptr, g0, s2);
  finalize_kernel<<<1,256>>>(s2, gg0, gbe0, a2, c2, 256, 1.f/(64.f*1024.f));
  k_dec1<<<dim3(16,4,64),256>>>(g0, gw1, a2, c2, g1, s3);
  finalize_kernel<<<1,128>>>(s3, gg1, gbe1, a3, c3, 128, 1.f/(64.f*4096.f));
  deconv2_kernel<<<dim3(4,4,64),128>>>(g1, gw2, gb2, a3, c3, out);
}

// round 8
// speedup vs baseline: 8.0462x; 1.1556x over previous
#include <cuda_runtime.h>
#include <math.h>

#define TWO_PI_F 6.2831853071795864769f

// ---------------- device scratch ----------------
__device__ float d_h0[64*64*64*64];
__device__ float d_h1[64*128*32*32];
__device__ float d_Zbuf[64*168*16*16];
__device__ float d_g0[64*256*32*32];
__device__ float d_g1[64*128*64*64];
__device__ float d_stat0[128];
__device__ float d_stat1[256];
__device__ float d_stat2[512];
__device__ float d_stat3[256];
__device__ float d_a0[64],  d_c0[64];
__device__ float d_a1[128], d_c1[128];
__device__ float d_a2[256], d_c2[256];
__device__ float d_a3[128], d_c3[128];
// pre-transposed weights
__device__ float d_wTc0[3*16*64];
__device__ float d_wTc1[64*16*128];
__device__ float d_wTc2[128*16*64];
__device__ float d_wTd0[4*168*4*256];
__device__ float d_wTd1[4*256*4*128];

// ---------------- packed f32x2 helpers ----------------
__device__ __forceinline__ unsigned long long pk2(float lo, float hi){
  unsigned long long r; asm("mov.b64 %0, {%1, %2};" : "=l"(r) : "f"(lo), "f"(hi)); return r;
}
__device__ __forceinline__ void fma2(unsigned long long& d, unsigned long long a, unsigned long long b){
  asm("fma.rn.f32x2 %0, %1, %2, %0;" : "+l"(d) : "l"(a), "l"(b));
}
__device__ __forceinline__ void unpk(unsigned long long v, float& lo, float& hi){
  asm("mov.b64 {%0, %1}, %2;" : "=f"(lo), "=f"(hi) : "l"(v));
}

// =====================================================================
// Weight transposes (run each call; cheap, coalesced reads)
// conv:  w[co][ci][ky][kx]  ->  wT[ci][k][co]
// =====================================================================
__global__ void transpose_conv_w(const float* __restrict__ w, float* __restrict__ wT,
                                 int IC, int OC)
{
  int idx = blockIdx.x*256 + threadIdx.x;
  int total = OC*IC*16;
  if (idx >= total) return;
  int k  = idx % 16;
  int ci = (idx/16) % IC;
  int co = idx/(16*IC);
  wT[(ci*16 + k)*OC + co] = w[idx];
}

// deconv: w[ci][co][ky][kx] -> wT[par][ci][t4][co], par=ry*2+rx, t4=d*2+e,
// tap (3-ry-2d, 3-rx-2e) == (ky,kx)
__global__ void transpose_deconv_w(const float* __restrict__ w, float* __restrict__ wT,
                                   int IC, int OC)
{
  int idx = blockIdx.x*256 + threadIdx.x;
  int total = IC*OC*16;
  if (idx >= total) return;
  int kk = idx % 16;
  int co = (idx/16) % OC;
  int ci = idx/(16*OC);
  int ky = kk >> 2, kx = kk & 3;
  int ry = (3-ky) & 1, dd = (3-ky-ry) >> 1;
  int rx = (3-kx) & 1, ee = (3-kx-rx) >> 1;
  int par = ry*2 + rx, t4 = dd*2 + ee;
  wT[((par*IC + ci)*4 + t4)*OC + co] = w[idx];
}

// =====================================================================
// Strided conv k=4 s=2 p=1. Per thread: 8 ox x CO_T co (packed pairs).
// Weight staging from pre-transposed wT: coalesced LDG, conflict-free STS.
// =====================================================================
template<int IC, int OC, int IH, int IW, int OH, int OW, int OUT_CB,
         int TILE_OY, int CO_BLK, int CI_CHUNK, int NG_OX, int NG_CO,
         bool ACT_IN_LRELU, bool BIAS, bool TANH_OUT, bool REDUCE>
__global__ void __launch_bounds__(NG_CO*NG_OX*TILE_OY)
conv_s2_kernel(const float* __restrict__ in, const float* __restrict__ wT,
               const float* __restrict__ bias,
               const float* __restrict__ a_in, const float* __restrict__ c_in,
               float* __restrict__ out, float* __restrict__ stat)
{
  constexpr int NT    = NG_CO * NG_OX * TILE_OY;
  constexpr int CO_T  = CO_BLK / NG_CO;
  constexpr int CO_P  = CO_T / 2;
  constexpr int ROWS  = 2*TILE_OY + 2;
  constexpr int COLSP = IW + 4;
  static_assert(OW / NG_OX == 8, "");

  __shared__ __align__(16) float sIn[CI_CHUNK][ROWS][COLSP];
  __shared__ __align__(16) float sW [CI_CHUNK][16][CO_BLK];
  __shared__ float sRed[2*CO_BLK];

  const int tid   = threadIdx.x;
  const int co_g  = tid % NG_CO;
  const int ox_g  = (tid / NG_CO) % NG_OX;
  const int oy_l  = tid / (NG_CO * NG_OX);
  const int co_base = blockIdx.y * CO_BLK;
  const int b     = blockIdx.z;
  const int oy0   = blockIdx.x * TILE_OY;
  const int iy0   = 2*oy0 - 1;
  const int ox0   = ox_g * 8;
  const int co_t0 = co_g * CO_T;

  unsigned long long acc[8][CO_P];
  #pragma unroll
  for (int u=0;u<8;u++)
    #pragma unroll
    for (int j=0;j<CO_P;j++) acc[u][j] = 0ULL;

  for (int ci0 = 0; ci0 < IC; ci0 += CI_CHUNK) {
    for (int idx = tid; idx < CI_CHUNK*ROWS*COLSP; idx += NT) {
      int cc  = idx / (ROWS*COLSP);
      int rem = idx % (ROWS*COLSP);
      int r   = rem / COLSP, col = rem % COLSP;
      int iy  = iy0 + r, ix = col - 1;
      float v = 0.f;
      if (ix >= 0 && ix < IW && iy >= 0 && iy < IH) {
        v = in[((b*IC + ci0+cc)*IH + iy)*IW + ix];
        if constexpr (ACT_IN_LRELU) {
          float t = fmaf(a_in[ci0+cc], v, c_in[ci0+cc]);
          v = t > 0.f ? t : 0.2f*t;
        }
      }
      sIn[cc][r][col] = v;
    }
    // coalesced: co fastest, contiguous LDG from wT, contiguous STS
    for (int idx = tid; idx < CI_CHUNK*16*CO_BLK; idx += NT) {
      int cc  = idx / (16*CO_BLK);
      int rem = idx % (16*CO_BLK);
      int k   = rem / CO_BLK, co = rem % CO_BLK;
      sW[cc][k][co] = wT[((ci0+cc)*16 + k)*OC + co_base + co];
    }
    __syncthreads();

    #pragma unroll
    for (int cc=0; cc<CI_CHUNK; cc++) {
      #pragma unroll
      for (int k=0;k<16;k++) {
        const int ky = k >> 2, kx = k & 3;
        unsigned long long wv[CO_P];
        #pragma unroll
        for (int j=0;j<CO_P;j++)
          wv[j] = *reinterpret_cast<const unsigned long long*>(&sW[cc][k][co_t0 + 2*j]);
        const float* rowp = &sIn[cc][2*oy_l + ky][0];
        #pragma unroll
        for (int u=0;u<8;u++) {
          float iv = rowp[2*(ox0+u) + kx];
          unsigned long long pv = pk2(iv, iv);
          #pragma unroll
          for (int j=0;j<CO_P;j++) fma2(acc[u][j], pv, wv[j]);
        }
      }
    }
    __syncthreads();
  }

  if constexpr (REDUCE) {
    for (int i = tid; i < 2*CO_BLK; i += NT) sRed[i] = 0.f;
    __syncthreads();
  }

  const int oy = oy0 + oy_l;
  #pragma unroll
  for (int j=0;j<CO_P;j++){
    float v0[8], v1[8];
    #pragma unroll
    for (int u=0;u<8;u++) unpk(acc[u][j], v0[u], v1[u]);
    const int co = co_base + co_t0 + 2*j;
    if constexpr (BIAS) {
      float b0 = bias[co], b1 = bias[co+1];
      #pragma unroll
      for (int u=0;u<8;u++){ v0[u]+=b0; v1[u]+=b1; }
    }
    if constexpr (TANH_OUT) {
      #pragma unroll
      for (int u=0;u<8;u++){ v0[u]=tanhf(v0[u]); v1[u]=tanhf(v1[u]); }
    }
    float4* p0 = reinterpret_cast<float4*>(&out[((b*OUT_CB + co  )*OH + oy)*OW + ox0]);
    float4* p1 = reinterpret_cast<float4*>(&out[((b*OUT_CB + co+1)*OH + oy)*OW + ox0]);
    p0[0] = make_float4(v0[0],v0[1],v0[2],v0[3]);
    p0[1] = make_float4(v0[4],v0[5],v0[6],v0[7]);
    p1[0] = make_float4(v1[0],v1[1],v1[2],v1[3]);
    p1[1] = make_float4(v1[4],v1[5],v1[6],v1[7]);
    if constexpr (REDUCE) {
      float s0=0.f,q0=0.f,s1=0.f,q1=0.f;
      #pragma unroll
      for (int u=0;u<8;u++){ s0+=v0[u]; q0=fmaf(v0[u],v0[u],q0); s1+=v1[u]; q1=fmaf(v1[u],v1[u],q1); }
      int cl = co_t0 + 2*j;
      atomicAdd(&sRed[cl],          s0);
      atomicAdd(&sRed[CO_BLK+cl],   q0);
      atomicAdd(&sRed[cl+1],        s1);
      atomicAdd(&sRed[CO_BLK+cl+1], q1);
    }
  }
  if constexpr (REDUCE) {
    __syncthreads();
    if (tid < 2*CO_BLK) {
      int cl = (tid < CO_BLK) ? tid : (tid - CO_BLK);
      int off = (tid < CO_BLK) ? 0 : OC;
      atomicAdd(&stat[off + co_base + cl], sRed[tid]);
    }
  }
}

// =====================================================================
// Transposed conv k=4 s=2 p=1 via parity decomposition.
// Weight staging from pre-transposed wdT[par][ci][t4][co]: coalesced.
// =====================================================================
template<int IC, int OC, int IH, int IW, int OUT_CB,
         int TILE_M, int CO_BLK, int CI_CHUNK, int NG_N, int NG_CO,
         bool ACT_IN_RELU, bool REDUCE>
__global__ void __launch_bounds__(NG_N*NG_CO*TILE_M)
deconv_kernel(const float* __restrict__ in, const float* __restrict__ wT,
              const float* __restrict__ a_in, const float* __restrict__ c_in,
              float* __restrict__ out, float* __restrict__ stat)
{
  constexpr int NT    = NG_N * NG_CO * TILE_M;
  constexpr int CO_T  = CO_BLK / NG_CO;
  constexpr int CO_P  = CO_T / 2;
  constexpr int ROWS  = TILE_M + 1;
  constexpr int COLSP = IW + 2;
  constexpr int NCO_G = OC / CO_BLK;
  static_assert(IW / NG_N == 8, "");

  __shared__ __align__(16) float sIn[CI_CHUNK][ROWS][COLSP];
  __shared__ __align__(16) float sW [CI_CHUNK][4][CO_BLK];
  __shared__ float sRed[2*CO_BLK];

  const int tid    = threadIdx.x;
  const int n_g    = tid % NG_N;
  const int co_g   = (tid / NG_N) % NG_CO;
  const int m_l    = tid / (NG_N * NG_CO);
  const int co_grp = blockIdx.x % NCO_G;
  const int m_tile = blockIdx.x / NCO_G;
  const int ry     = blockIdx.y >> 1, rx = blockIdx.y & 1;
  const int par    = blockIdx.y;
  const int b      = blockIdx.z;
  const int m0     = m_tile * TILE_M;
  const int co_base= co_grp * CO_BLK;
  const int n0     = n_g * 8;
  const int co_t0  = co_g * CO_T;

  unsigned long long acc[8][CO_P];
  #pragma unroll
  for (int u=0;u<8;u++)
    #pragma unroll
    for (int j=0;j<CO_P;j++) acc[u][j] = 0ULL;

  for (int ci0 = 0; ci0 < IC; ci0 += CI_CHUNK) {
    for (int idx = tid; idx < CI_CHUNK*ROWS*COLSP; idx += NT) {
      int cc  = idx / (ROWS*COLSP);
      int rem = idx % (ROWS*COLSP);
      int r   = rem / COLSP, col = rem % COLSP;
      int gy  = m0 + ry - 1 + r;
      int gx  = rx - 1 + col;
      float v = 0.f;
      if (gy >= 0 && gy < IH && gx >= 0 && gx < IW) {
        v = in[((b*IC + ci0+cc)*IH + gy)*IW + gx];
        if constexpr (ACT_IN_RELU)
          v = fmaxf(fmaf(a_in[ci0+cc], v, c_in[ci0+cc]), 0.f);
      }
      sIn[cc][r][col] = v;
    }
    // coalesced: co fastest
    for (int idx = tid; idx < CI_CHUNK*4*CO_BLK; idx += NT) {
      int cc  = idx / (4*CO_BLK);
      int rem = idx % (4*CO_BLK);
      int t4  = rem / CO_BLK, co = rem % CO_BLK;
      sW[cc][t4][co] = wT[((par*IC + ci0+cc)*4 + t4)*OC + co_base + co];
    }
    __syncthreads();

    #pragma unroll
    for (int cc=0; cc<CI_CHUNK; cc++) {
      #pragma unroll
      for (int t4=0;t4<4;t4++) {
        const int dd = t4 >> 1, ee = t4 & 1;
        unsigned long long wv[CO_P];
        #pragma unroll
        for (int j=0;j<CO_P;j++)
          wv[j] = *reinterpret_cast<const unsigned long long*>(&sW[cc][t4][co_t0 + 2*j]);
        const float* rowp = &sIn[cc][m_l + dd][0];
        #pragma unroll
        for (int u=0;u<8;u++) {
          float iv = rowp[n0 + u + ee];
          unsigned long long pv = pk2(iv, iv);
          #pragma unroll
          for (int j=0;j<CO_P;j++) fma2(acc[u][j], pv, wv[j]);
        }
      }
    }
    __syncthreads();
  }

  if constexpr (REDUCE) {
    for (int i = tid; i < 2*CO_BLK; i += NT) sRed[i] = 0.f;
    __syncthreads();
  }

  const int oy = 2*(m0 + m_l) + ry;
  const int OW2 = 2*IW, OH2 = 2*IH;
  #pragma unroll
  for (int j=0;j<CO_P;j++){
    const int co = co_base + co_t0 + 2*j;
    float* r0 = &out[((b*OUT_CB + co  )*OH2 + oy)*OW2 + rx];
    float* r1 = &out[((b*OUT_CB + co+1)*OH2 + oy)*OW2 + rx];
    float s0=0.f,q0=0.f,s1=0.f,q1=0.f;
    #pragma unroll
    for (int u=0;u<8;u++){
      float v0, v1; unpk(acc[u][j], v0, v1);
      r0[2*(n0+u)] = v0;
      r1[2*(n0+u)] = v1;
      if constexpr (REDUCE) { s0+=v0; q0=fmaf(v0,v0,q0); s1+=v1; q1=fmaf(v1,v1,q1); }
    }
    if constexpr (REDUCE) {
      int cl = co_t0 + 2*j;
      atomicAdd(&sRed[cl],          s0);
      atomicAdd(&sRed[CO_BLK+cl],   q0);
      atomicAdd(&sRed[cl+1],        s1);
      atomicAdd(&sRed[CO_BLK+cl+1], q1);
    }
  }
  if constexpr (REDUCE) {
    __syncthreads();
    if (tid < 2*CO_BLK) {
      int cl = (tid < CO_BLK) ? tid : (tid - CO_BLK);
      int off = (tid < CO_BLK) ? 0 : OC;
      atomicAdd(&stat[off + co_base + cl], sRed[tid]);
    }
  }
}

// =====================================================================
// Final deconv 128->3 with bias + tanh
// =====================================================================
__global__ void __launch_bounds__(128)
deconv2_kernel(const float* __restrict__ in, const float* __restrict__ w,
               const float* __restrict__ bias,
               const float* __restrict__ a_in, const float* __restrict__ c_in,
               float* __restrict__ out)
{
  constexpr int IC=128, IH=64, IW=64, TILE_M=16, CI=4, NG_N=8;
  constexpr int NT=128, ROWS=TILE_M+1, COLSP=IW+2;
  __shared__ float sIn[CI][ROWS][COLSP];
  __shared__ float sW[CI][4][4];

  const int tid = threadIdx.x;
  const int n_g = tid % NG_N;
  const int m_l = tid / NG_N;
  const int m0  = blockIdx.x * TILE_M;
  const int ry  = blockIdx.y >> 1, rx = blockIdx.y & 1;
  const int b   = blockIdx.z;
  const int n0  = n_g * 8;

  float acc[3][8];
  #pragma unroll
  for (int co=0;co<3;co++)
    #pragma unroll
    for (int u=0;u<8;u++) acc[co][u] = 0.f;

  for (int ci0 = 0; ci0 < IC; ci0 += CI) {
    for (int idx = tid; idx < CI*ROWS*COLSP; idx += NT) {
      int cc  = idx / (ROWS*COLSP);
      int rem = idx % (ROWS*COLSP);
      int r   = rem / COLSP, col = rem % COLSP;
      int gy  = m0 + ry - 1 + r;
      int gx  = rx - 1 + col;
      float v = 0.f;
      if (gy >= 0 && gy < IH && gx >= 0 && gx < IW)
        v = fmaxf(fmaf(a_in[ci0+cc], in[((b*IC + ci0+cc)*IH + gy)*IW + gx], c_in[ci0+cc]), 0.f);
      sIn[cc][r][col] = v;
    }
    if (tid < 48) {
      int cc = tid / 12, t4 = (tid / 3) % 4, co = tid % 3;
      int dd = t4 >> 1, ee = t4 & 1;
      sW[cc][t4][co] = w[((ci0+cc)*3 + co)*16 + (3-ry-2*dd)*4 + (3-rx-2*ee)];
    }
    __syncthreads();

    #pragma unroll
    for (int cc=0; cc<CI; cc++) {
      #pragma unroll
      for (int t4=0;t4<4;t4++) {
        const int dd = t4 >> 1, ee = t4 & 1;
        float w0 = sW[cc][t4][0], w1 = sW[cc][t4][1], w2 = sW[cc][t4][2];
        const float* rowp = &sIn[cc][m_l + dd][0];
        #pragma unroll
        for (int u=0;u<8;u++) {
          float iv = rowp[n0 + u + ee];
          acc[0][u] = fmaf(iv, w0, acc[0][u]);
          acc[1][u] = fmaf(iv, w1, acc[1][u]);
          acc[2][u] = fmaf(iv, w2, acc[2][u]);
        }
      }
    }
    __syncthreads();
  }

  const int oy = 2*(m0 + m_l) + ry;
  #pragma unroll
  for (int co=0;co<3;co++){
    float bb = bias[co];
    float* rp = &out[((b*3 + co)*128 + oy)*128 + rx];
    #pragma unroll
    for (int u=0;u<8;u++)
      rp[2*(n0+u)] = tanhf(acc[co][u] + bb);
  }
}

// =====================================================================
__global__ void finalize_kernel(const float* __restrict__ stat, const float* __restrict__ g,
                                const float* __restrict__ be,
                                float* __restrict__ a, float* __restrict__ cv,
                                int C, float invN)
{
  int c = threadIdx.x + blockIdx.x*blockDim.x;
  if (c >= C) return;
  float mean = stat[c] * invN;
  float var  = stat[C + c] * invN - mean*mean;
  float av = g[c] * rsqrtf(var + 1e-5f);
  a[c] = av;
  cv[c] = be[c] - mean * av;
}

__global__ void zero_kernel(float* s0, float* s1, float* s2, float* s3)
{
  int t = threadIdx.x;
  if (t < 128) s0[t] = 0.f;
  if (t < 256) s1[t] = 0.f;
  if (t < 512) s2[t] = 0.f;
  if (t < 256) s3[t] = 0.f;
}

__global__ void pack_kernel(const float* __restrict__ Zl, const float* __restrict__ Zg,
                            float* __restrict__ Zbuf)
{
  int idx = blockIdx.x * 256 + threadIdx.x;
  const int nl = 64*32*256;
  if (idx < nl) {
    int b = idx / (32*256); int r = idx % (32*256);
    Zbuf[(b*168 + 64)*256 + r] = Zl[idx];
  }
  const int ng = 64*64*256;
  if (idx < ng) {
    int b = idx / (64*256); int r = idx % (64*256);
    Zbuf[(b*168 + 96)*256 + r] = Zg[idx];
  }
}

__global__ void wave_kernel(const float* __restrict__ Zg, const float* __restrict__ phi,
                            const float* __restrict__ lW, const float* __restrict__ lb,
                            const float* __restrict__ l1W, const float* __restrict__ l1b,
                            const float* __restrict__ l2W, const float* __restrict__ l2b,
                            float* __restrict__ Zbuf)
{
  const int b = blockIdx.x;
  const int t = threadIdx.x;  // 64
  __shared__ float zg[64], x[64], K[16];
  zg[t] = Zg[(b*64 + t)*256];
  __syncthreads();
  float acc = lb[t];
  #pragma unroll 8
  for (int g = 0; g < 64; g++) acc = fmaf(zg[g], lW[t*64+g], acc);
  x[t] = fmaxf(acc, 0.f);
  __syncthreads();
  if (t < 16) {
    int p = t & 7;
    const float* W  = (t < 8) ? l1W : l2W;
    const float* bb = (t < 8) ? l1b : l2b;
    float k = bb[p];
    #pragma unroll 8
    for (int h = 0; h < 64; h++) k = fmaf(x[h], W[p*64+h], k);
    K[t] = k;
  }
  __syncthreads();
  for (int idx = t; idx < 8*256; idx += 64) {
    int p = idx >> 8; int ij = idx & 255; int i = ij >> 4; int j = ij & 15;
    float wv = K[p]*(float)i + K[p+8]*(float)j + phi[b*8+p]*TWO_PI_F;
    Zbuf[(b*168 + 160 + p)*256 + ij] = sinf(wv);
  }
}

// =====================================================================
extern "C" void kernel_launch(void* const* d_in, const int* in_sizes, int n_in,
                              void* d_out, int out_size)
{
  const float* Zl   = (const float*)d_in[0];
  const float* Zg   = (const float*)d_in[1];
  const float* imgs = (const float*)d_in[2];
  const float* phi  = (const float*)d_in[3];
  const float* lW   = (const float*)d_in[4];
  const float* lb   = (const float*)d_in[5];
  const float* l1W  = (const float*)d_in[6];
  const float* l1b  = (const float*)d_in[7];
  const float* l2W  = (const float*)d_in[8];
  const float* l2b  = (const float*)d_in[9];
  const float* cw0  = (const float*)d_in[10];
  const float* cg0  = (const float*)d_in[12];
  const float* cbe0 = (const float*)d_in[13];
  const float* cw1  = (const float*)d_in[14];
  const float* cg1  = (const float*)d_in[16];
  const float* cbe1 = (const float*)d_in[17];
  const float* cw2  = (const float*)d_in[18];
  const float* cb2  = (const float*)d_in[19];
  const float* gw0  = (const float*)d_in[20];
  const float* gg0  = (const float*)d_in[22];
  const float* gbe0 = (const float*)d_in[23];
  const float* gw1  = (const float*)d_in[24];
  const float* gg1  = (const float*)d_in[26];
  const float* gbe1 = (const float*)d_in[27];
  const float* gw2  = (const float*)d_in[28];
  const float* gb2  = (const float*)d_in[29];
  float* out = (float*)d_out;

  float *h0,*h1,*Zb,*g0,*g1;
  float *s0,*s1,*s2,*s3;
  float *a0,*c0,*a1,*c1,*a2,*c2,*a3,*c3;
  float *wTc0,*wTc1,*wTc2,*wTd0,*wTd1;
  cudaGetSymbolAddress((void**)&h0, d_h0);
  cudaGetSymbolAddress((void**)&h1, d_h1);
  cudaGetSymbolAddress((void**)&Zb, d_Zbuf);
  cudaGetSymbolAddress((void**)&g0, d_g0);
  cudaGetSymbolAddress((void**)&g1, d_g1);
  cudaGetSymbolAddress((void**)&s0, d_stat0);
  cudaGetSymbolAddress((void**)&s1, d_stat1);
  cudaGetSymbolAddress((void**)&s2, d_stat2);
  cudaGetSymbolAddress((void**)&s3, d_stat3);
  cudaGetSymbolAddress((void**)&a0, d_a0); cudaGetSymbolAddress((void**)&c0, d_c0);
  cudaGetSymbolAddress((void**)&a1, d_a1); cudaGetSymbolAddress((void**)&c1, d_c1);
  cudaGetSymbolAddress((void**)&a2, d_a2); cudaGetSymbolAddress((void**)&c2, d_c2);
  cudaGetSymbolAddress((void**)&a3, d_a3); cudaGetSymbolAddress((void**)&c3, d_c3);
  cudaGetSymbolAddress((void**)&wTc0, d_wTc0);
  cudaGetSymbolAddress((void**)&wTc1, d_wTc1);
  cudaGetSymbolAddress((void**)&wTc2, d_wTc2);
  cudaGetSymbolAddress((void**)&wTd0, d_wTd0);
  cudaGetSymbolAddress((void**)&wTd1, d_wTd1);

  zero_kernel<<<1,512>>>(s0, s1, s2, s3);
  // weight transposes (coalesced staging for all heavy layers)
  transpose_conv_w<<<(3*64*16+255)/256,256>>>(cw0, wTc0, 3, 64);
  transpose_conv_w<<<(64*128*16+255)/256,256>>>(cw1, wTc1, 64, 128);
  transpose_conv_w<<<(128*64*16+255)/256,256>>>(cw2, wTc2, 128, 64);
  transpose_deconv_w<<<(168*256*16+255)/256,256>>>(gw0, wTd0, 168, 256);
  transpose_deconv_w<<<(256*128*16+255)/256,256>>>(gw1, wTd1, 256, 128);
  pack_kernel<<<4096,256>>>(Zl, Zg, Zb);
  wave_kernel<<<64,64>>>(Zg, phi, lW, lb, l1W, l1b, l2W, l2b, Zb);

  // encoder (stats fused)
  conv_s2_kernel<3,64,128,128,64,64, 64, 4,64,3,8,8, false,false,false,true>
      <<<dim3(16,1,64),256>>>(imgs, wTc0, nullptr, nullptr, nullptr, h0, s0);
  finalize_kernel<<<1,64>>>(s0, cg0, cbe0, a0, c0, 64, 1.f/(64.f*4096.f));
  conv_s2_kernel<64,128,64,64,32,32, 128, 8,64,4,4,8, true,false,false,true>
      <<<dim3(4,2,64),256>>>(h0, wTc1, nullptr, a0, c0, h1, s1);
  finalize_kernel<<<1,128>>>(s1, cg1, cbe1, a1, c1, 128, 1.f/(64.f*1024.f));
  conv_s2_kernel<128,64,32,32,16,16, 168, 8,64,4,2,16, true,true,true,false>
      <<<dim3(2,1,64),256>>>(h1, wTc2, cb2, a1, c1, Zb, nullptr);

  // generator (stats fused)
  deconv_kernel<168,256,16,16, 256, 8,128,8,2,16, false,true>
      <<<dim3(4,4,64),256>>>(Zb, wTd0, nullptr, nullptr, g0, s2);
  finalize_kernel<<<1,256>>>(s2, gg0, gbe0, a2, c2, 256, 1.f/(64.f*1024.f));
  deconv_kernel<256,128,32,32, 128, 8,128,8,4,16, true,true>
      <<<dim3(4,4,64),512>>>(g0, wTd1, a2, c2, g1, s3);
  finalize_kernel<<<1,128>>>(s3, gg1, gbe1, a3, c3, 128, 1.f/(64.f*4096.f));
  deconv2_kernel<<<dim3(4,4,64),128>>>(g1, gw2, gb2, a3, c3, out);
}

// round 9
// speedup vs baseline: 9.4301x; 1.1720x over previous
#include <cuda_runtime.h>
#include <math.h>

#define TWO_PI_F 6.2831853071795864769f

// ---------------- device scratch ----------------
__device__ float d_h0[64*64*64*64];
__device__ float d_h1[64*128*32*32];
__device__ float d_Zbuf[64*168*16*16];
__device__ float d_g0[64*256*32*32];
__device__ float d_g1[64*128*64*64];
__device__ float d_stat0[128];
__device__ float d_stat1[256];
__device__ float d_stat2[512];
__device__ float d_stat3[256];
__device__ float d_a0[64],  d_c0[64];
__device__ float d_a1[128], d_c1[128];
__device__ float d_a2[256], d_c2[256];
__device__ float d_a3[128], d_c3[128];
// pre-transposed weights
__device__ float d_wTc0[3*16*64];
__device__ float d_wTc1[64*16*128];
__device__ float d_wTc2[128*16*64];
__device__ float d_wTd0[4*168*4*256];
__device__ float d_wTd1[4*256*4*128];

// ---------------- packed f32x2 helpers ----------------
__device__ __forceinline__ unsigned long long pk2(float lo, float hi){
  unsigned long long r; asm("mov.b64 %0, {%1, %2};" : "=l"(r) : "f"(lo), "f"(hi)); return r;
}
__device__ __forceinline__ void fma2(unsigned long long& d, unsigned long long a, unsigned long long b){
  asm("fma.rn.f32x2 %0, %1, %2, %0;" : "+l"(d) : "l"(a), "l"(b));
}
__device__ __forceinline__ void unpk(unsigned long long v, float& lo, float& hi){
  asm("mov.b64 {%0, %1}, %2;" : "=f"(lo), "=f"(hi) : "l"(v));
}

// =====================================================================
// Merged weight transposes
// conv:  w[co][ci][k] -> wT[ci][k][co]
// =====================================================================
__device__ __forceinline__ void tconv(const float* __restrict__ w, float* __restrict__ wT,
                                      int IC, int OC, int idx){
  int k = idx % 16; int ci = (idx/16) % IC; int co = idx/(16*IC);
  wT[(ci*16+k)*OC + co] = w[idx];
}
__device__ __forceinline__ void tdec(const float* __restrict__ w, float* __restrict__ wT,
                                     int IC, int OC, int idx){
  int kk = idx%16; int co = (idx/16)%OC; int ci = idx/(16*OC);
  int ky=kk>>2, kx=kk&3;
  int ry=(3-ky)&1, dd=(3-ky-ry)>>1;
  int rx=(3-kx)&1, ee=(3-kx-rx)>>1;
  wT[(((ry*2+rx)*IC+ci)*4 + dd*2+ee)*OC + co] = w[idx];
}
__global__ void transpose_convs(const float* w0, float* o0, const float* w1, float* o1,
                                const float* w2, float* o2){
  int idx = blockIdx.x*256 + threadIdx.x;
  if (idx < 3*64*16)   tconv(w0,o0,3,64,idx);
  if (idx < 64*128*16) tconv(w1,o1,64,128,idx);
  if (idx < 128*64*16) tconv(w2,o2,128,64,idx);
}
__global__ void transpose_deconvs(const float* w0, float* o0, const float* w1, float* o1){
  int idx = blockIdx.x*256+threadIdx.x;
  if (idx < 168*256*16) tdec(w0,o0,168,256,idx);
  if (idx < 256*128*16) tdec(w1,o1,256,128,idx);
}

// =====================================================================
// Strided conv k=4 s=2 p=1. CO_BLK == OC: weight chunk is a pure linear
// float4 copy. Input staging offsets precomputed (ci0-invariant).
// =====================================================================
template<int IC, int OC, int IH, int IW, int OH, int OW, int OUT_CB,
         int TILE_OY, int CO_BLK, int CI_CHUNK, int NG_OX, int NG_CO,
         bool ACT_IN_LRELU, bool BIAS, bool TANH_OUT, bool REDUCE>
__global__ void __launch_bounds__(NG_CO*NG_OX*TILE_OY)
conv_s2_kernel(const float* __restrict__ in, const float* __restrict__ wT,
               const float* __restrict__ bias,
               const float* __restrict__ a_in, const float* __restrict__ c_in,
               float* __restrict__ out, float* __restrict__ stat)
{
  constexpr int NT    = NG_CO * NG_OX * TILE_OY;
  constexpr int CO_T  = CO_BLK / NG_CO;
  constexpr int CO_P  = CO_T / 2;
  constexpr int ROWS  = 2*TILE_OY + 2;
  constexpr int COLSP = IW + 4;
  constexpr int TOTAL_IN = CI_CHUNK*ROWS*COLSP;
  constexpr int NITER = (TOTAL_IN + NT - 1)/NT;
  constexpr int WLEN4 = CI_CHUNK*16*CO_BLK/4;
  static_assert(OW / NG_OX == 8, "");
  static_assert(CO_BLK == OC, "");
  static_assert((CO_P & (CO_P-1)) == 0, "");

  __shared__ __align__(16) float sIn[CI_CHUNK][ROWS][COLSP];
  __shared__ __align__(16) float sW [CI_CHUNK][16][CO_BLK];
  __shared__ float sRed[2*CO_BLK];

  const int tid   = threadIdx.x;
  const int co_g  = tid % NG_CO;
  const int ox_g  = (tid / NG_CO) % NG_OX;
  const int oy_l  = tid / (NG_CO * NG_OX);
  const int b     = blockIdx.z;
  const int oy0   = blockIdx.x * TILE_OY;
  const int iy0   = 2*oy0 - 1;
  const int ox0   = ox_g * 8;
  const int co_t0 = co_g * CO_T;

  // precompute staging offsets (ci0-invariant)
  int gOff[NITER]; int ccA[NITER];
  #pragma unroll
  for (int i=0;i<NITER;i++){
    int idx = tid + i*NT;
    int cc  = idx / (ROWS*COLSP);
    int rem = idx % (ROWS*COLSP);
    int r   = rem / COLSP, col = rem % COLSP;
    int iy  = iy0 + r, ix = col - 1;
    bool ok = (idx < TOTAL_IN) && ix >= 0 && ix < IW && iy >= 0 && iy < IH;
    gOff[i] = ok ? ((b*IC + cc)*IH + iy)*IW + ix : -1;
    ccA[i]  = cc;
  }

  unsigned long long acc[8][CO_P];
  #pragma unroll
  for (int u=0;u<8;u++)
    #pragma unroll
    for (int j=0;j<CO_P;j++) acc[u][j] = 0ULL;

  float* sInF = &sIn[0][0][0];

  for (int ci0 = 0; ci0 < IC; ci0 += CI_CHUNK) {
    const int cBase = ci0*IH*IW;
    #pragma unroll
    for (int i=0;i<NITER;i++){
      int idx = tid + i*NT;
      if (idx < TOTAL_IN) {
        float v = 0.f;
        int go = gOff[i];
        if (go >= 0) {
          v = in[go + cBase];
          if constexpr (ACT_IN_LRELU) {
            float t = fmaf(a_in[ci0+ccA[i]], v, c_in[ci0+ccA[i]]);
            v = t > 0.f ? t : 0.2f*t;
          }
        }
        sInF[idx] = v;
      }
    }
    // linear weight copy: chunk contiguous in wT and in sW
    {
      const float4* ws = reinterpret_cast<const float4*>(wT + ci0*16*OC);
      float4* wd = reinterpret_cast<float4*>(&sW[0][0][0]);
      #pragma unroll
      for (int i = 0; i < (WLEN4 + NT - 1)/NT; i++) {
        int idx = tid + i*NT;
        if (idx < WLEN4) wd[idx] = ws[idx];
      }
    }
    __syncthreads();

    #pragma unroll
    for (int cc=0; cc<CI_CHUNK; cc++) {
      #pragma unroll
      for (int k=0;k<16;k++) {
        const int ky = k >> 2, kx = k & 3;
        unsigned long long wv[CO_P];
        #pragma unroll
        for (int j=0;j<CO_P;j++){
          int p = (j + co_g) & (CO_P-1);
          wv[j] = *reinterpret_cast<const unsigned long long*>(&sW[cc][k][co_t0 + 2*p]);
        }
        const float* rowp = &sIn[cc][2*oy_l + ky][0];
        #pragma unroll
        for (int u=0;u<8;u++) {
          float iv = rowp[2*(ox0+u) + kx];
          unsigned long long pv = pk2(iv, iv);
          #pragma unroll
          for (int j=0;j<CO_P;j++) fma2(acc[u][j], pv, wv[j]);
        }
      }
    }
    __syncthreads();
  }

  if constexpr (REDUCE) {
    for (int i = tid; i < 2*CO_BLK; i += NT) sRed[i] = 0.f;
    __syncthreads();
  }

  const int oy = oy0 + oy_l;
  #pragma unroll
  for (int j=0;j<CO_P;j++){
    int p = (j + co_g) & (CO_P-1);
    float v0[8], v1[8];
    #pragma unroll
    for (int u=0;u<8;u++) unpk(acc[u][j], v0[u], v1[u]);
    const int co = co_t0 + 2*p;
    if constexpr (BIAS) {
      float b0 = bias[co], b1 = bias[co+1];
      #pragma unroll
      for (int u=0;u<8;u++){ v0[u]+=b0; v1[u]+=b1; }
    }
    if constexpr (TANH_OUT) {
      #pragma unroll
      for (int u=0;u<8;u++){ v0[u]=tanhf(v0[u]); v1[u]=tanhf(v1[u]); }
    }
    float4* p0 = reinterpret_cast<float4*>(&out[((b*OUT_CB + co  )*OH + oy)*OW + ox0]);
    float4* p1 = reinterpret_cast<float4*>(&out[((b*OUT_CB + co+1)*OH + oy)*OW + ox0]);
    p0[0] = make_float4(v0[0],v0[1],v0[2],v0[3]);
    p0[1] = make_float4(v0[4],v0[5],v0[6],v0[7]);
    p1[0] = make_float4(v1[0],v1[1],v1[2],v1[3]);
    p1[1] = make_float4(v1[4],v1[5],v1[6],v1[7]);
    if constexpr (REDUCE) {
      float s0=0.f,q0=0.f,s1=0.f,q1=0.f;
      #pragma unroll
      for (int u=0;u<8;u++){ s0+=v0[u]; q0=fmaf(v0[u],v0[u],q0); s1+=v1[u]; q1=fmaf(v1[u],v1[u],q1); }
      atomicAdd(&sRed[co],          s0);
      atomicAdd(&sRed[CO_BLK+co],   q0);
      atomicAdd(&sRed[co+1],        s1);
      atomicAdd(&sRed[CO_BLK+co+1], q1);
    }
  }
  if constexpr (REDUCE) {
    __syncthreads();
    for (int i2 = tid; i2 < 2*CO_BLK; i2 += NT) {
      int off = (i2 < CO_BLK) ? 0 : OC;
      int cl  = (i2 < CO_BLK) ? i2 : (i2 - CO_BLK);
      atomicAdd(&stat[off + cl], sRed[i2]);
    }
  }
}

// =====================================================================
// Transposed conv k=4 s=2 p=1 via parity decomposition. CO_BLK == OC.
// =====================================================================
template<int IC, int OC, int IH, int IW, int OUT_CB,
         int TILE_M, int CO_BLK, int CI_CHUNK, int NG_N, int NG_CO,
         bool ACT_IN_RELU, bool REDUCE>
__global__ void __launch_bounds__(NG_N*NG_CO*TILE_M)
deconv_kernel(const float* __restrict__ in, const float* __restrict__ wT,
              const float* __restrict__ a_in, const float* __restrict__ c_in,
              float* __restrict__ out, float* __restrict__ stat)
{
  constexpr int NT    = NG_N * NG_CO * TILE_M;
  constexpr int CO_T  = CO_BLK / NG_CO;
  constexpr int CO_P  = CO_T / 2;
  constexpr int ROWS  = TILE_M + 1;
  constexpr int COLSP = IW + 2;
  constexpr int TOTAL_IN = CI_CHUNK*ROWS*COLSP;
  constexpr int NITER = (TOTAL_IN + NT - 1)/NT;
  constexpr int WLEN4 = CI_CHUNK*4*CO_BLK/4;
  static_assert(IW / NG_N == 8, "");
  static_assert(CO_BLK == OC, "");
  static_assert((CO_P & (CO_P-1)) == 0, "");

  __shared__ __align__(16) float sIn[CI_CHUNK][ROWS][COLSP];
  __shared__ __align__(16) float sW [CI_CHUNK][4][CO_BLK];
  __shared__ float sRed[2*CO_BLK];

  const int tid    = threadIdx.x;
  const int n_g    = tid % NG_N;
  const int co_g   = (tid / NG_N) % NG_CO;
  const int m_l    = tid / (NG_N * NG_CO);
  const int m_tile = blockIdx.x;
  const int ry     = blockIdx.y >> 1, rx = blockIdx.y & 1;
  const int par    = blockIdx.y;
  const int b      = blockIdx.z;
  const int m0     = m_tile * TILE_M;
  const int n0     = n_g * 8;
  const int co_t0  = co_g * CO_T;

  int gOff[NITER]; int ccA[NITER];
  #pragma unroll
  for (int i=0;i<NITER;i++){
    int idx = tid + i*NT;
    int cc  = idx / (ROWS*COLSP);
    int rem = idx % (ROWS*COLSP);
    int r   = rem / COLSP, col = rem % COLSP;
    int gy  = m0 + ry - 1 + r;
    int gx  = rx - 1 + col;
    bool ok = (idx < TOTAL_IN) && gx >= 0 && gx < IW && gy >= 0 && gy < IH;
    gOff[i] = ok ? ((b*IC + cc)*IH + gy)*IW + gx : -1;
    ccA[i]  = cc;
  }

  unsigned long long acc[8][CO_P];
  #pragma unroll
  for (int u=0;u<8;u++)
    #pragma unroll
    for (int j=0;j<CO_P;j++) acc[u][j] = 0ULL;

  float* sInF = &sIn[0][0][0];

  for (int ci0 = 0; ci0 < IC; ci0 += CI_CHUNK) {
    const int cBase = ci0*IH*IW;
    #pragma unroll
    for (int i=0;i<NITER;i++){
      int idx = tid + i*NT;
      if (idx < TOTAL_IN) {
        float v = 0.f;
        int go = gOff[i];
        if (go >= 0) {
          v = in[go + cBase];
          if constexpr (ACT_IN_RELU)
            v = fmaxf(fmaf(a_in[ci0+ccA[i]], v, c_in[ci0+ccA[i]]), 0.f);
        }
        sInF[idx] = v;
      }
    }
    {
      const float4* ws = reinterpret_cast<const float4*>(wT + (par*IC + ci0)*4*OC);
      float4* wd = reinterpret_cast<float4*>(&sW[0][0][0]);
      #pragma unroll
      for (int i = 0; i < (WLEN4 + NT - 1)/NT; i++) {
        int idx = tid + i*NT;
        if (idx < WLEN4) wd[idx] = ws[idx];
      }
    }
    __syncthreads();

    #pragma unroll
    for (int cc=0; cc<CI_CHUNK; cc++) {
      #pragma unroll
      for (int t4=0;t4<4;t4++) {
        const int dd = t4 >> 1, ee = t4 & 1;
        unsigned long long wv[CO_P];
        #pragma unroll
        for (int j=0;j<CO_P;j++){
          int p = (j + co_g) & (CO_P-1);
          wv[j] = *reinterpret_cast<const unsigned long long*>(&sW[cc][t4][co_t0 + 2*p]);
        }
        const float* rowp = &sIn[cc][m_l + dd][0];
        #pragma unroll
        for (int u=0;u<8;u++) {
          float iv = rowp[n0 + u + ee];
          unsigned long long pv = pk2(iv, iv);
          #pragma unroll
          for (int j=0;j<CO_P;j++) fma2(acc[u][j], pv, wv[j]);
        }
      }
    }
    __syncthreads();
  }

  if constexpr (REDUCE) {
    for (int i = tid; i < 2*CO_BLK; i += NT) sRed[i] = 0.f;
    __syncthreads();
  }

  const int oy = 2*(m0 + m_l) + ry;
  const int OW2 = 2*IW, OH2 = 2*IH;
  #pragma unroll
  for (int j=0;j<CO_P;j++){
    int p = (j + co_g) & (CO_P-1);
    const int co = co_t0 + 2*p;
    float* r0 = &out[((b*OUT_CB + co  )*OH2 + oy)*OW2 + rx];
    float* r1 = &out[((b*OUT_CB + co+1)*OH2 + oy)*OW2 + rx];
    float s0=0.f,q0=0.f,s1=0.f,q1=0.f;
    #pragma unroll
    for (int u=0;u<8;u++){
      float v0, v1; unpk(acc[u][j], v0, v1);
      r0[2*(n0+u)] = v0;
      r1[2*(n0+u)] = v1;
      if constexpr (REDUCE) { s0+=v0; q0=fmaf(v0,v0,q0); s1+=v1; q1=fmaf(v1,v1,q1); }
    }
    if constexpr (REDUCE) {
      atomicAdd(&sRed[co],          s0);
      atomicAdd(&sRed[CO_BLK+co],   q0);
      atomicAdd(&sRed[co+1],        s1);
      atomicAdd(&sRed[CO_BLK+co+1], q1);
    }
  }
  if constexpr (REDUCE) {
    __syncthreads();
    for (int i2 = tid; i2 < 2*CO_BLK; i2 += NT) {
      int off = (i2 < CO_BLK) ? 0 : OC;
      int cl  = (i2 < CO_BLK) ? i2 : (i2 - CO_BLK);
      atomicAdd(&stat[off + cl], sRed[i2]);
    }
  }
}

// =====================================================================
// Final deconv 128->3 with bias + tanh
// =====================================================================
__global__ void __launch_bounds__(128)
deconv2_kernel(const float* __restrict__ in, const float* __restrict__ w,
               const float* __restrict__ bias,
               const float* __restrict__ a_in, const float* __restrict__ c_in,
               float* __restrict__ out)
{
  constexpr int IC=128, IH=64, IW=64, TILE_M=16, CI=4, NG_N=8;
  constexpr int NT=128, ROWS=TILE_M+1, COLSP=IW+2;
  constexpr int TOTAL_IN = CI*ROWS*COLSP;
  constexpr int NITER = (TOTAL_IN + NT - 1)/NT;
  __shared__ float sIn[CI][ROWS][COLSP];
  __shared__ float sW[CI][4][4];

  const int tid = threadIdx.x;
  const int n_g = tid % NG_N;
  const int m_l = tid / NG_N;
  const int m0  = blockIdx.x * TILE_M;
  const int ry  = blockIdx.y >> 1, rx = blockIdx.y & 1;
  const int b   = blockIdx.z;
  const int n0  = n_g * 8;

  int gOff[NITER]; int ccA[NITER];
  #pragma unroll
  for (int i=0;i<NITER;i++){
    int idx = tid + i*NT;
    int cc  = idx / (ROWS*COLSP);
    int rem = idx % (ROWS*COLSP);
    int r   = rem / COLSP, col = rem % COLSP;
    int gy  = m0 + ry - 1 + r;
    int gx  = rx - 1 + col;
    bool ok = (idx < TOTAL_IN) && gx >= 0 && gx < IW && gy >= 0 && gy < IH;
    gOff[i] = ok ? ((b*IC + cc)*IH + gy)*IW + gx : -1;
    ccA[i]  = cc;
  }

  float acc[3][8];
  #pragma unroll
  for (int co=0;co<3;co++)
    #pragma unroll
    for (int u=0;u<8;u++) acc[co][u] = 0.f;

  float* sInF = &sIn[0][0][0];

  for (int ci0 = 0; ci0 < IC; ci0 += CI) {
    const int cBase = ci0*IH*IW;
    #pragma unroll
    for (int i=0;i<NITER;i++){
      int idx = tid + i*NT;
      if (idx < TOTAL_IN) {
        float v = 0.f;
        int go = gOff[i];
        if (go >= 0)
          v = fmaxf(fmaf(a_in[ci0+ccA[i]], in[go + cBase], c_in[ci0+ccA[i]]), 0.f);
        sInF[idx] = v;
      }
    }
    if (tid < 48) {
      int cc = tid / 12, t4 = (tid / 3) % 4, co = tid % 3;
      int dd = t4 >> 1, ee = t4 & 1;
      sW[cc][t4][co] = w[((ci0+cc)*3 + co)*16 + (3-ry-2*dd)*4 + (3-rx-2*ee)];
    }
    __syncthreads();

    #pragma unroll
    for (int cc=0; cc<CI; cc++) {
      #pragma unroll
      for (int t4=0;t4<4;t4++) {
        const int dd = t4 >> 1, ee = t4 & 1;
        float w0 = sW[cc][t4][0], w1 = sW[cc][t4][1], w2 = sW[cc][t4][2];
        const float* rowp = &sIn[cc][m_l + dd][0];
        #pragma unroll
        for (int u=0;u<8;u++) {
          float iv = rowp[n0 + u + ee];
          acc[0][u] = fmaf(iv, w0, acc[0][u]);
          acc[1][u] = fmaf(iv, w1, acc[1][u]);
          acc[2][u] = fmaf(iv, w2, acc[2][u]);
        }
      }
    }
    __syncthreads();
  }

  const int oy = 2*(m0 + m_l) + ry;
  #pragma unroll
  for (int co=0;co<3;co++){
    float bb = bias[co];
    float* rp = &out[((b*3 + co)*128 + oy)*128 + rx];
    #pragma unroll
    for (int u=0;u<8;u++)
      rp[2*(n0+u)] = tanhf(acc[co][u] + bb);
  }
}

// =====================================================================
__global__ void finalize_kernel(const float* __restrict__ stat, const float* __restrict__ g,
                                const float* __restrict__ be,
                                float* __restrict__ a, float* __restrict__ cv,
                                int C, float invN)
{
  int c = threadIdx.x + blockIdx.x*blockDim.x;
  if (c >= C) return;
  float mean = stat[c] * invN;
  float var  = stat[C + c] * invN - mean*mean;
  float av = g[c] * rsqrtf(var + 1e-5f);
  a[c] = av;
  cv[c] = be[c] - mean * av;
}

__global__ void zero_kernel(float* s0, float* s1, float* s2, float* s3)
{
  int t = threadIdx.x;
  if (t < 128) s0[t] = 0.f;
  if (t < 256) s1[t] = 0.f;
  if (t < 512) s2[t] = 0.f;
  if (t < 256) s3[t] = 0.f;
}

__global__ void pack_kernel(const float* __restrict__ Zl, const float* __restrict__ Zg,
                            float* __restrict__ Zbuf)
{
  int idx = blockIdx.x * 256 + threadIdx.x;
  const int nl = 64*32*256;
  if (idx < nl) {
    int b = idx / (32*256); int r = idx % (32*256);
    Zbuf[(b*168 + 64)*256 + r] = Zl[idx];
  }
  const int ng = 64*64*256;
  if (idx < ng) {
    int b = idx / (64*256); int r = idx % (64*256);
    Zbuf[(b*168 + 96)*256 + r] = Zg[idx];
  }
}

__global__ void wave_kernel(const float* __restrict__ Zg, const float* __restrict__ phi,
                            const float* __restrict__ lW, const float* __restrict__ lb,
                            const float* __restrict__ l1W, const float* __restrict__ l1b,
                            const float* __restrict__ l2W, const float* __restrict__ l2b,
                            float* __restrict__ Zbuf)
{
  const int b = blockIdx.x;
  const int t = threadIdx.x;  // 64
  __shared__ float zg[64], x[64], K[16];
  zg[t] = Zg[(b*64 + t)*256];
  __syncthreads();
  float acc = lb[t];
  #pragma unroll 8
  for (int g = 0; g < 64; g++) acc = fmaf(zg[g], lW[t*64+g], acc);
  x[t] = fmaxf(acc, 0.f);
  __syncthreads();
  if (t < 16) {
    int p = t & 7;
    const float* W  = (t < 8) ? l1W : l2W;
    const float* bb = (t < 8) ? l1b : l2b;
    float k = bb[p];
    #pragma unroll 8
    for (int h = 0; h < 64; h++) k = fmaf(x[h], W[p*64+h], k);
    K[t] = k;
  }
  __syncthreads();
  for (int idx = t; idx < 8*256; idx += 64) {
    int p = idx >> 8; int ij = idx & 255; int i = ij >> 4; int j = ij & 15;
    float wv = K[p]*(float)i + K[p+8]*(float)j + phi[b*8+p]*TWO_PI_F;
    Zbuf[(b*168 + 160 + p)*256 + ij] = sinf(wv);
  }
}

// =====================================================================
extern "C" void kernel_launch(void* const* d_in, const int* in_sizes, int n_in,
                              void* d_out, int out_size)
{
  const float* Zl   = (const float*)d_in[0];
  const float* Zg   = (const float*)d_in[1];
  const float* imgs = (const float*)d_in[2];
  const float* phi  = (const float*)d_in[3];
  const float* lW   = (const float*)d_in[4];
  const float* lb   = (const float*)d_in[5];
  const float* l1W  = (const float*)d_in[6];
  const float* l1b  = (const float*)d_in[7];
  const float* l2W  = (const float*)d_in[8];
  const float* l2b  = (const float*)d_in[9];
  const float* cw0  = (const float*)d_in[10];
  const float* cg0  = (const float*)d_in[12];
  const float* cbe0 = (const float*)d_in[13];
  const float* cw1  = (const float*)d_in[14];
  const float* cg1  = (const float*)d_in[16];
  const float* cbe1 = (const float*)d_in[17];
  const float* cw2  = (const float*)d_in[18];
  const float* cb2  = (const float*)d_in[19];
  const float* gw0  = (const float*)d_in[20];
  const float* gg0  = (const float*)d_in[22];
  const float* gbe0 = (const float*)d_in[23];
  const float* gw1  = (const float*)d_in[24];
  const float* gg1  = (const float*)d_in[26];
  const float* gbe1 = (const float*)d_in[27];
  const float* gw2  = (const float*)d_in[28];
  const float* gb2  = (const float*)d_in[29];
  float* out = (float*)d_out;

  float *h0,*h1,*Zb,*g0,*g1;
  float *s0,*s1,*s2,*s3;
  float *a0,*c0,*a1,*c1,*a2,*c2,*a3,*c3;
  float *wTc0,*wTc1,*wTc2,*wTd0,*wTd1;
  cudaGetSymbolAddress((void**)&h0, d_h0);
  cudaGetSymbolAddress((void**)&h1, d_h1);
  cudaGetSymbolAddress((void**)&Zb, d_Zbuf);
  cudaGetSymbolAddress((void**)&g0, d_g0);
  cudaGetSymbolAddress((void**)&g1, d_g1);
  cudaGetSymbolAddress((void**)&s0, d_stat0);
  cudaGetSymbolAddress((void**)&s1, d_stat1);
  cudaGetSymbolAddress((void**)&s2, d_stat2);
  cudaGetSymbolAddress((void**)&s3, d_stat3);
  cudaGetSymbolAddress((void**)&a0, d_a0); cudaGetSymbolAddress((void**)&c0, d_c0);
  cudaGetSymbolAddress((void**)&a1, d_a1); cudaGetSymbolAddress((void**)&c1, d_c1);
  cudaGetSymbolAddress((void**)&a2, d_a2); cudaGetSymbolAddress((void**)&c2, d_c2);
  cudaGetSymbolAddress((void**)&a3, d_a3); cudaGetSymbolAddress((void**)&c3, d_c3);
  cudaGetSymbolAddress((void**)&wTc0, d_wTc0);
  cudaGetSymbolAddress((void**)&wTc1, d_wTc1);
  cudaGetSymbolAddress((void**)&wTc2, d_wTc2);
  cudaGetSymbolAddress((void**)&wTd0, d_wTd0);
  cudaGetSymbolAddress((void**)&wTd1, d_wTd1);

  // order chosen so ncu -s 5 -c 1 captures conv0
  zero_kernel<<<1,512>>>(s0, s1, s2, s3);                       // 0
  pack_kernel<<<4096,256>>>(Zl, Zg, Zb);                        // 1
  wave_kernel<<<64,64>>>(Zg, phi, lW, lb, l1W, l1b, l2W, l2b, Zb); // 2
  transpose_convs<<<512,256>>>(cw0, wTc0, cw1, wTc1, cw2, wTc2);   // 3
  transpose_deconvs<<<2688,256>>>(gw0, wTd0, gw1, wTd1);           // 4

  // encoder (stats fused)
  conv_s2_kernel<3,64,128,128,64,64, 64, 4,64,3,8,8, false,false,false,true>
      <<<dim3(16,1,64),256>>>(imgs, wTc0, nullptr, nullptr, nullptr, h0, s0);   // 5
  finalize_kernel<<<1,64>>>(s0, cg0, cbe0, a0, c0, 64, 1.f/(64.f*4096.f));
  conv_s2_kernel<64,128,64,64,32,32, 128, 8,128,2,4,8, true,false,false,true>
      <<<dim3(4,1,64),256>>>(h0, wTc1, nullptr, a0, c0, h1, s1);
  finalize_kernel<<<1,128>>>(s1, cg1, cbe1, a1, c1, 128, 1.f/(64.f*1024.f));
  conv_s2_kernel<128,64,32,32,16,16, 168, 8,64,4,2,16, true,true,true,false>
      <<<dim3(2,1,64),256>>>(h1, wTc2, cb2, a1, c1, Zb, nullptr);

  // generator (stats fused)
  deconv_kernel<168,256,16,16, 256, 8,256,8,2,16, false,true>
      <<<dim3(2,4,64),256>>>(Zb, wTd0, nullptr, nullptr, g0, s2);
  finalize_kernel<<<1,256>>>(s2, gg0, gbe0, a2, c2, 256, 1.f/(64.f*1024.f));
  deconv_kernel<256,128,32,32, 128, 8,128,8,4,16, true,true>
      <<<dim3(4,4,64),512>>>(g0, wTd1, a2, c2, g1, s3);
  finalize_kernel<<<1,128>>>(s3, gg1, gbe1, a3, c3, 128, 1.f/(64.f*4096.f));
  deconv2_kernel<<<dim3(4,4,64),128>>>(g1, gw2, gb2, a3, c3, out);
}